// round 1
// baseline (speedup 1.0000x reference)
#include <cuda_runtime.h>
#include <math.h>

#define NN   50000
#define EE   400000
#define IND  256
#define HIDD 128
#define TT   3
#define RR   4
#define HH   8
#define DKK  16
#define NPERM_SZ 50432   // 394 blocks * 128

// ---------------- scratch (static device globals; no runtime alloc) ----------
__device__ float d_h0[NN*HIDD];
__device__ float d_h1[NN*HIDD];
__device__ float d_kb[NN*HIDD];
__device__ float d_qb[NN*HIDD];
__device__ float d_vb[NN*HIDD];
__device__ float d_krel[(size_t)NN*RR*HIDD];
__device__ float d_vrel[(size_t)NN*RR*HIDD];
__device__ float d_agg[NN*HIDD];
__device__ float d_gelu[NN*HIDD];
__device__ float d_trans[NN*HIDD];
__device__ int   d_deg[NN];
__device__ int   d_off[NN+1];
__device__ int   d_cursor[NN];
__device__ int   d_eperm[EE];
__device__ int   d_bsum[256];
__device__ int   d_bpre[256];
__device__ int   d_tcnt[TT];
__device__ int   d_topad[TT+1];
__device__ int   d_tcur[TT];
__device__ int   d_nperm[NPERM_SZ];

// ---------------- setup kernels ----------------------------------------------
__global__ void k_init() {
    int i = blockIdx.x*blockDim.x + threadIdx.x;
    if (i < NPERM_SZ) d_nperm[i] = -1;
    if (i < NN)       d_deg[i]   = 0;
    if (i < TT)       d_tcnt[i]  = 0;
}

__global__ void k_count(const int* __restrict__ ntypes, const int* __restrict__ dst) {
    int i = blockIdx.x*blockDim.x + threadIdx.x;
    if (i < NN) atomicAdd(&d_tcnt[ntypes[i]], 1);
    if (i < EE) atomicAdd(&d_deg[dst[i]], 1);
}

__global__ void k_toffsets() {
    // single thread
    int run = 0;
    for (int t = 0; t < TT; t++) {
        d_topad[t] = run;
        d_tcur[t]  = run;
        run += ((d_tcnt[t] + 127) / 128) * 128;
    }
    d_topad[TT] = run;
}

__global__ void k_scatter_nodes(const int* __restrict__ ntypes) {
    int i = blockIdx.x*blockDim.x + threadIdx.x;
    if (i < NN) {
        int t = ntypes[i];
        int p = atomicAdd(&d_tcur[t], 1);
        d_nperm[p] = i;
    }
}

__device__ __forceinline__ int block_scan_incl(int x, int* wsum) {
    unsigned full = 0xffffffffu;
    int lane = threadIdx.x & 31, wid = threadIdx.x >> 5;
    int v = x;
    #pragma unroll
    for (int d = 1; d < 32; d <<= 1) {
        int t = __shfl_up_sync(full, v, d);
        if (lane >= d) v += t;
    }
    if (lane == 31) wsum[wid] = v;
    __syncthreads();
    if (threadIdx.x == 0) {
        int run = 0;
        #pragma unroll
        for (int w = 0; w < 8; w++) { int t = wsum[w]; wsum[w] = run; run += t; }
    }
    __syncthreads();
    return v + wsum[wid];
}

__global__ void k_scan1() {
    __shared__ int wsum[8];
    int i = blockIdx.x*256 + threadIdx.x;
    int x = (i < NN) ? d_deg[i] : 0;
    int inc = block_scan_incl(x, wsum);
    if (i < NN) d_off[i] = inc - x;           // local exclusive
    if (threadIdx.x == 255) d_bsum[blockIdx.x] = inc;
}

__global__ void k_scan2(int nblocks) {
    __shared__ int wsum[8];
    int t = threadIdx.x;
    int x = (t < nblocks) ? d_bsum[t] : 0;
    int inc = block_scan_incl(x, wsum);
    if (t < 256) d_bpre[t] = inc - x;         // exclusive block prefix
}

__global__ void k_scan3() {
    int i = blockIdx.x*256 + threadIdx.x;
    if (i < NN) {
        int v = d_off[i] + d_bpre[i >> 8];
        d_off[i]    = v;
        d_cursor[i] = v;
    }
    if (i == 0) d_off[NN] = EE;
}

__global__ void k_scatter_edges(const int* __restrict__ dst) {
    int e = blockIdx.x*blockDim.x + threadIdx.x;
    if (e < EE) {
        int p = atomicAdd(&d_cursor[dst[e]], 1);
        d_eperm[p] = e;
    }
}

// ---------------- typed SGEMM body --------------------------------------------
// C[nperm[row]] = act(A[nperm[row]] @ W[type] + b[type]), tile 128x128, BK=16.
template<int KDIM, int ACT>
__device__ __forceinline__ void gemm_body(const float* __restrict__ A,
                                          const float* __restrict__ W,
                                          const float* __restrict__ bias,
                                          float* __restrict__ C) {
    __shared__ float As[16][128];
    __shared__ float Bs[16][128];
    const int base = blockIdx.x * 128;
    const int t = (base >= d_topad[1]) + (base >= d_topad[2]);
    const float* Wt = W + (size_t)t * KDIM * 128;
    const float* bt = bias + t * 128;
    const int tid = threadIdx.x;
    const int ty = tid >> 4, tx = tid & 15;

    const int am = tid >> 1;
    const int ak = (tid & 1) * 8;
    const int arow = d_nperm[base + am];

    const int bidx0 = tid * 2;
    const int bk0 = bidx0 >> 5, bn0 = (bidx0 & 31) * 4;
    const int bk1 = (bidx0+1) >> 5, bn1 = ((bidx0+1) & 31) * 4;

    float acc[8][8];
    #pragma unroll
    for (int i = 0; i < 8; i++)
        #pragma unroll
        for (int j = 0; j < 8; j++) acc[i][j] = 0.f;

    for (int kt = 0; kt < KDIM/16; kt++) {
        const int k0 = kt * 16;
        float4 a0 = make_float4(0.f,0.f,0.f,0.f), a1 = a0;
        if (arow >= 0) {
            const float* ap = A + (size_t)arow * KDIM + k0 + ak;
            a0 = *(const float4*)ap;
            a1 = *(const float4*)(ap + 4);
        }
        As[ak+0][am]=a0.x; As[ak+1][am]=a0.y; As[ak+2][am]=a0.z; As[ak+3][am]=a0.w;
        As[ak+4][am]=a1.x; As[ak+5][am]=a1.y; As[ak+6][am]=a1.z; As[ak+7][am]=a1.w;

        *(float4*)&Bs[bk0][bn0] = *(const float4*)&Wt[(size_t)(k0+bk0)*128 + bn0];
        *(float4*)&Bs[bk1][bn1] = *(const float4*)&Wt[(size_t)(k0+bk1)*128 + bn1];
        __syncthreads();

        #pragma unroll
        for (int k = 0; k < 16; k++) {
            float ar[8], br[8];
            *(float4*)(ar)   = *(float4*)&As[k][ty*8];
            *(float4*)(ar+4) = *(float4*)&As[k][ty*8+4];
            *(float4*)(br)   = *(float4*)&Bs[k][tx*8];
            *(float4*)(br+4) = *(float4*)&Bs[k][tx*8+4];
            #pragma unroll
            for (int i = 0; i < 8; i++)
                #pragma unroll
                for (int j = 0; j < 8; j++)
                    acc[i][j] = fmaf(ar[i], br[j], acc[i][j]);
        }
        __syncthreads();
    }

    #pragma unroll
    for (int i = 0; i < 8; i++) {
        int row = d_nperm[base + ty*8 + i];
        if (row < 0) continue;
        float o[8];
        #pragma unroll
        for (int j = 0; j < 8; j++) {
            float v = acc[i][j] + bt[tx*8 + j];
            if (ACT == 1) v = tanhf(v);
            o[j] = v;
        }
        float* cp = C + (size_t)row * 128 + tx*8;
        *(float4*)cp     = *(float4*)(o);
        *(float4*)(cp+4) = *(float4*)(o+4);
    }
}

__global__ void __launch_bounds__(256) k_gemm_adapt(const float* __restrict__ x,
                                                    const float* __restrict__ W,
                                                    const float* __restrict__ b) {
    gemm_body<IND, 1>(x, W, b, d_h0);
}

__global__ void __launch_bounds__(256) k_gemm_kqv(int which_in,
        const float* __restrict__ Wk, const float* __restrict__ bk,
        const float* __restrict__ Wq, const float* __restrict__ bq,
        const float* __restrict__ Wv, const float* __restrict__ bv) {
    const float* A = which_in ? d_h1 : d_h0;
    if (blockIdx.y == 0)      gemm_body<HIDD,0>(A, Wk, bk, d_kb);
    else if (blockIdx.y == 1) gemm_body<HIDD,0>(A, Wq, bq, d_qb);
    else                      gemm_body<HIDD,0>(A, Wv, bv, d_vb);
}

__global__ void __launch_bounds__(256) k_gemm_att(const float* __restrict__ Wa,
                                                  const float* __restrict__ ba) {
    gemm_body<HIDD, 0>(d_gelu, Wa, ba, d_trans);
}

// ---------------- per-node relation transforms --------------------------------
// blockIdx.y in [0,8): slot = r*2 + isV.  krel[n][r][h][f] = sum_d k[n][h][d]*W[r][h][d][f]
__global__ void k_reltrans(const float* __restrict__ Ratt, const float* __restrict__ Rmsg) {
    const int slot = blockIdx.y;
    const int r = slot >> 1;
    const bool isV = slot & 1;
    const float* srcv = isV ? d_vb : d_kb;
    float* dstv = isV ? d_vrel : d_krel;
    const float* Wh = (isV ? Rmsg : Ratt) + r*HH*DKK*DKK;

    const int lane = threadIdx.x & 31;
    const int wid  = threadIdx.x >> 5;
    const int h = lane >> 2;
    const int f0 = (lane & 3) * 4;
    const float* Wp = Wh + h*256;

    float4 w[16];
    #pragma unroll
    for (int d = 0; d < 16; d++) w[d] = *(const float4*)(Wp + d*16 + f0);

    const int wpb = blockDim.x >> 5;
    for (int n = blockIdx.x*wpb + wid; n < NN; n += gridDim.x*wpb) {
        const float4* row = (const float4*)(srcv + (size_t)n*128) + h*4;
        float4 q0 = row[0], q1 = row[1], q2 = row[2], q3 = row[3];
        float4 acc = make_float4(0.f,0.f,0.f,0.f);
        #define RMAC(qc, d) acc.x=fmaf(qc,w[d].x,acc.x); acc.y=fmaf(qc,w[d].y,acc.y); \
                            acc.z=fmaf(qc,w[d].z,acc.z); acc.w=fmaf(qc,w[d].w,acc.w);
        RMAC(q0.x,0)  RMAC(q0.y,1)  RMAC(q0.z,2)  RMAC(q0.w,3)
        RMAC(q1.x,4)  RMAC(q1.y,5)  RMAC(q1.z,6)  RMAC(q1.w,7)
        RMAC(q2.x,8)  RMAC(q2.y,9)  RMAC(q2.z,10) RMAC(q2.w,11)
        RMAC(q3.x,12) RMAC(q3.y,13) RMAC(q3.z,14) RMAC(q3.w,15)
        #undef RMAC
        ((float4*)dstv)[((size_t)n*RR + r)*32 + lane] = acc;
    }
}

// ---------------- edge phase: warp-per-dst, online softmax --------------------
__global__ void k_edge(const int* __restrict__ srcArr, const int* __restrict__ etArr,
                       const float* __restrict__ pri) {
    const int warp = (blockIdx.x*blockDim.x + threadIdx.x) >> 5;
    if (warp >= NN) return;
    const int lane = threadIdx.x & 31;
    const int grp = lane >> 2;
    const unsigned full = 0xffffffffu;

    float4 q4 = ((const float4*)d_qb)[(size_t)warp*32 + lane];
    const int beg = d_off[warp], end = d_off[warp+1];

    float m = -1e30f, s = 0.f;
    float4 acc = make_float4(0.f,0.f,0.f,0.f);

    for (int e = beg; e < end; e++) {
        int eid = d_eperm[e];
        int sn = srcArr[eid];
        int r  = etArr[eid];
        size_t bidx = ((size_t)sn*RR + r)*32 + lane;
        float4 k4 = ((const float4*)d_krel)[bidx];
        float4 v4 = ((const float4*)d_vrel)[bidx];
        float p = q4.x*k4.x + q4.y*k4.y + q4.z*k4.z + q4.w*k4.w;
        p += __shfl_xor_sync(full, p, 1);
        p += __shfl_xor_sync(full, p, 2);
        float l = p * __ldg(&pri[r*HH + grp]) * 0.25f;
        float mn = fmaxf(m, l);
        float corr = __expf(m - mn);
        float w = __expf(l - mn);
        s = s*corr + w;
        acc.x = fmaf(w, v4.x, acc.x*corr);
        acc.y = fmaf(w, v4.y, acc.y*corr);
        acc.z = fmaf(w, v4.z, acc.z*corr);
        acc.w = fmaf(w, v4.w, acc.w*corr);
        m = mn;
    }
    float inv = 1.0f / fmaxf(s, 1e-9f);
    acc.x *= inv; acc.y *= inv; acc.z *= inv; acc.w *= inv;
    ((float4*)d_agg)[(size_t)warp*32 + lane] = acc;
}

// ---------------- elementwise -------------------------------------------------
__global__ void k_gelu() {
    int i = blockIdx.x*blockDim.x + threadIdx.x;
    if (i < NN*HIDD/4) {
        float4 v = ((const float4*)d_agg)[i];
        float4 g;
        g.x = 0.5f*v.x*(1.0f + erff(v.x*0.70710678118654752f));
        g.y = 0.5f*v.y*(1.0f + erff(v.y*0.70710678118654752f));
        g.z = 0.5f*v.z*(1.0f + erff(v.z*0.70710678118654752f));
        g.w = 0.5f*v.w*(1.0f + erff(v.w*0.70710678118654752f));
        ((float4*)d_gelu)[i] = g;
    }
}

// layer1: skip + LayerNorm(per-type) + ReLU -> d_h1
__global__ void k_combine1(const int* __restrict__ ntypes,
                           const float* __restrict__ skip,
                           const float* __restrict__ gamma,
                           const float* __restrict__ beta) {
    const int n = (blockIdx.x*blockDim.x + threadIdx.x) >> 5;
    if (n >= NN) return;
    const int lane = threadIdx.x & 31;
    const unsigned full = 0xffffffffu;
    int t = ntypes[n];
    float alpha = 1.0f / (1.0f + __expf(-skip[t]));
    float4 tr = ((const float4*)d_trans)[(size_t)n*32 + lane];
    float4 hx = ((const float4*)d_h0)[(size_t)n*32 + lane];
    float ia = 1.0f - alpha;
    float4 o;
    o.x = tr.x*alpha + hx.x*ia;
    o.y = tr.y*alpha + hx.y*ia;
    o.z = tr.z*alpha + hx.z*ia;
    o.w = tr.w*alpha + hx.w*ia;
    float sm = o.x + o.y + o.z + o.w;
    float sq = o.x*o.x + o.y*o.y + o.z*o.z + o.w*o.w;
    #pragma unroll
    for (int d = 16; d; d >>= 1) {
        sm += __shfl_xor_sync(full, sm, d);
        sq += __shfl_xor_sync(full, sq, d);
    }
    float mean = sm * (1.0f/128.0f);
    float var  = sq * (1.0f/128.0f) - mean*mean;
    float rstd = rsqrtf(var + 1e-5f);
    float4 g4 = ((const float4*)gamma)[t*32 + lane];
    float4 b4 = ((const float4*)beta)[t*32 + lane];
    float4 y;
    y.x = fmaxf((o.x-mean)*rstd*g4.x + b4.x, 0.f);
    y.y = fmaxf((o.y-mean)*rstd*g4.y + b4.y, 0.f);
    y.z = fmaxf((o.z-mean)*rstd*g4.z + b4.z, 0.f);
    y.w = fmaxf((o.w-mean)*rstd*g4.w + b4.w, 0.f);
    ((float4*)d_h1)[(size_t)n*32 + lane] = y;
}

// layer2: skip only -> out
__global__ void k_combine2(const int* __restrict__ ntypes,
                           const float* __restrict__ skip,
                           float* __restrict__ out) {
    int i = blockIdx.x*blockDim.x + threadIdx.x;
    if (i < NN*32) {
        int n = i >> 5;
        int t = ntypes[n];
        float alpha = 1.0f / (1.0f + __expf(-skip[t]));
        float ia = 1.0f - alpha;
        float4 tr = ((const float4*)d_trans)[i];
        float4 hx = ((const float4*)d_h1)[i];
        float4 o;
        o.x = tr.x*alpha + hx.x*ia;
        o.y = tr.y*alpha + hx.y*ia;
        o.z = tr.z*alpha + hx.z*ia;
        o.w = tr.w*alpha + hx.w*ia;
        ((float4*)out)[i] = o;
    }
}

// ---------------- launch ------------------------------------------------------
extern "C" void kernel_launch(void* const* d_in, const int* in_sizes, int n_in,
                              void* d_out, int out_size) {
    const float* x      = (const float*)d_in[0];
    const int*   ntypes = (const int*)d_in[1];
    const int*   ei     = (const int*)d_in[2];
    const int*   et     = (const int*)d_in[3];
    const float* Wad    = (const float*)d_in[4];
    const float* bad    = (const float*)d_in[5];
    const float* Wk     = (const float*)d_in[6];
    const float* bk     = (const float*)d_in[7];
    const float* Wq     = (const float*)d_in[8];
    const float* bq     = (const float*)d_in[9];
    const float* Wv     = (const float*)d_in[10];
    const float* bv     = (const float*)d_in[11];
    const float* Wa     = (const float*)d_in[12];
    const float* ba     = (const float*)d_in[13];
    const float* pri    = (const float*)d_in[14];
    const float* ratt   = (const float*)d_in[15];
    const float* rmsg   = (const float*)d_in[16];
    const float* skip   = (const float*)d_in[17];
    const float* gamma  = (const float*)d_in[18];
    const float* beta   = (const float*)d_in[19];
    float* out = (float*)d_out;

    const int* srcA = ei;
    const int* dstA = ei + EE;

    const int SCAN_BLK = (NN + 255) / 256;           // 196
    const int GEMM_BLK = NPERM_SZ / 128;             // 394
    const int WARP_BLK = (NN*32 + 255) / 256;        // 6250
    const int VEC_BLK  = (NN*32 + 255) / 256;        // float4 elementwise

    // ---- graph preprocessing (shared by both layers) ----
    k_init<<<(NPERM_SZ+255)/256, 256>>>();
    k_count<<<(EE+255)/256, 256>>>(ntypes, dstA);
    k_toffsets<<<1, 1>>>();
    k_scatter_nodes<<<(NN+255)/256, 256>>>(ntypes);
    k_scan1<<<SCAN_BLK, 256>>>();
    k_scan2<<<1, 256>>>(SCAN_BLK);
    k_scan3<<<SCAN_BLK, 256>>>();
    k_scatter_edges<<<(EE+255)/256, 256>>>(dstA);

    // ---- adapt: h0 = tanh(typed_linear(x)) ----
    k_gemm_adapt<<<GEMM_BLK, 256>>>(x, Wad, bad);

    const int LW = TT*HIDD*HIDD;   // per-layer typed-weight stride
    const int LB = TT*HIDD;
    const int LP = RR*HH;
    const int LR = RR*HH*DKK*DKK;

    for (int l = 0; l < 2; l++) {
        k_gemm_kqv<<<dim3(GEMM_BLK,3), 256>>>(l,
            Wk + (size_t)l*LW, bk + l*LB,
            Wq + (size_t)l*LW, bq + l*LB,
            Wv + (size_t)l*LW, bv + l*LB);
        k_reltrans<<<dim3(296, 8), 256>>>(ratt + (size_t)l*LR, rmsg + (size_t)l*LR);
        k_edge<<<WARP_BLK, 256>>>(srcA, et, pri + l*LP);
        k_gelu<<<VEC_BLK, 256>>>();
        k_gemm_att<<<GEMM_BLK, 256>>>(Wa + (size_t)l*LW, ba + l*LB);
        if (l == 0) {
            k_combine1<<<WARP_BLK, 256>>>(ntypes, skip + l*TT, gamma, beta);
        } else {
            k_combine2<<<VEC_BLK, 256>>>(ntypes, skip + l*TT, out);
        }
    }
}

// round 3
// speedup vs baseline: 1.3003x; 1.3003x over previous
#include <cuda_runtime.h>
#include <cuda_bf16.h>
#include <cstdint>
#include <math.h>

#define NN   50000
#define EE   400000
#define IND  256
#define HIDD 128
#define TT   3
#define RR   4
#define HH   8
#define DKK  16
#define NP   50432          // 394 blocks * 128
#define NTILE 394
#define NCHUNKS 30          // weight pack chunks

// ---------------- scratch (static device globals) -----------------------------
__device__ float d_h0[NP*HIDD];
__device__ float d_h1[NP*HIDD];
__device__ float d_kb[NP*HIDD];
__device__ float d_qb[NP*HIDD];
__device__ float d_vb[NP*HIDD];
__device__ float d_agg[NP*HIDD];
__device__ float d_trans[NP*HIDD];
__device__ float d_krel[(size_t)NP*RR*HIDD];
__device__ float d_vrel[(size_t)NP*RR*HIDD];
__device__ __nv_bfloat16 d_wpack_hi[NCHUNKS*16384];
__device__ __nv_bfloat16 d_wpack_lo[NCHUNKS*16384];
__device__ int   d_deg[NN];
__device__ int   d_off[NN+1];
__device__ int   d_cursor[NN];
__device__ int   d_epack[EE];
__device__ int   d_bsum[256];
__device__ int   d_bpre[256];
__device__ int   d_tcnt[TT];
__device__ int   d_topad[TT+1];
__device__ int   d_tcur[TT];
__device__ int   d_nperm[NP];
__device__ int   d_iperm[NN];

// ---------------- warp MMA helpers (sm_80+ PTX, works on compute_103) ---------
__device__ __forceinline__ uint32_t smem_u32(const void* p) {
    uint32_t a;
    asm("{ .reg .u64 t; cvta.to.shared.u64 t, %1; cvt.u32.u64 %0, t; }" : "=r"(a) : "l"(p));
    return a;
}
__device__ __forceinline__ void ldmatrix_x4(uint32_t* r, uint32_t addr) {
    asm volatile("ldmatrix.sync.aligned.m8n8.x4.shared.b16 {%0,%1,%2,%3}, [%4];"
                 : "=r"(r[0]), "=r"(r[1]), "=r"(r[2]), "=r"(r[3]) : "r"(addr));
}
__device__ __forceinline__ void ldmatrix_x2(uint32_t* r, uint32_t addr) {
    asm volatile("ldmatrix.sync.aligned.m8n8.x2.shared.b16 {%0,%1}, [%2];"
                 : "=r"(r[0]), "=r"(r[1]) : "r"(addr));
}
__device__ __forceinline__ void mma16816(float* d, const uint32_t* a, const uint32_t* b) {
    asm volatile("mma.sync.aligned.m16n8k16.row.col.f32.bf16.bf16.f32 "
                 "{%0,%1,%2,%3}, {%4,%5,%6,%7}, {%8,%9}, {%0,%1,%2,%3};"
                 : "+f"(d[0]), "+f"(d[1]), "+f"(d[2]), "+f"(d[3])
                 : "r"(a[0]), "r"(a[1]), "r"(a[2]), "r"(a[3]), "r"(b[0]), "r"(b[1]));
}

// ---------------- setup kernels ------------------------------------------------
__global__ void k_init() {
    int i = blockIdx.x*blockDim.x + threadIdx.x;
    if (i < NP) d_nperm[i] = -1;
    if (i < NN) d_deg[i] = 0;
    if (i < TT) d_tcnt[i] = 0;
}
__global__ void k_count(const int* __restrict__ ntypes, const int* __restrict__ dst) {
    int i = blockIdx.x*blockDim.x + threadIdx.x;
    if (i < NN) atomicAdd(&d_tcnt[ntypes[i]], 1);
    if (i < EE) atomicAdd(&d_deg[dst[i]], 1);
}
__global__ void k_toffsets() {
    int run = 0;
    for (int t = 0; t < TT; t++) {
        d_topad[t] = run; d_tcur[t] = run;
        run += ((d_tcnt[t] + 127) / 128) * 128;
    }
    d_topad[TT] = run;
}
__global__ void k_scatter_nodes(const int* __restrict__ ntypes) {
    int i = blockIdx.x*blockDim.x + threadIdx.x;
    if (i < NN) {
        int p = atomicAdd(&d_tcur[ntypes[i]], 1);
        d_nperm[p] = i;
        d_iperm[i] = p;
    }
}
__device__ __forceinline__ int block_scan_incl(int x, int* wsum) {
    unsigned full = 0xffffffffu;
    int lane = threadIdx.x & 31, wid = threadIdx.x >> 5;
    int v = x;
    #pragma unroll
    for (int d = 1; d < 32; d <<= 1) {
        int t = __shfl_up_sync(full, v, d);
        if (lane >= d) v += t;
    }
    if (lane == 31) wsum[wid] = v;
    __syncthreads();
    if (threadIdx.x == 0) {
        int run = 0;
        #pragma unroll
        for (int w = 0; w < 8; w++) { int t = wsum[w]; wsum[w] = run; run += t; }
    }
    __syncthreads();
    return v + wsum[wid];
}
__global__ void k_scan1() {
    __shared__ int wsum[8];
    int i = blockIdx.x*256 + threadIdx.x;
    int x = (i < NN) ? d_deg[i] : 0;
    int inc = block_scan_incl(x, wsum);
    if (i < NN) d_off[i] = inc - x;
    if (threadIdx.x == 255) d_bsum[blockIdx.x] = inc;
}
__global__ void k_scan2(int nblocks) {
    __shared__ int wsum[8];
    int t = threadIdx.x;
    int x = (t < nblocks) ? d_bsum[t] : 0;
    int inc = block_scan_incl(x, wsum);
    d_bpre[t] = inc - x;
}
__global__ void k_scan3() {
    int i = blockIdx.x*256 + threadIdx.x;
    if (i < NN) {
        int v = d_off[i] + d_bpre[i >> 8];
        d_off[i] = v; d_cursor[i] = v;
    }
    if (i == 0) d_off[NN] = EE;
}
__global__ void k_scatter_edges(const int* __restrict__ src, const int* __restrict__ dst,
                                const int* __restrict__ et) {
    int e = blockIdx.x*blockDim.x + threadIdx.x;
    if (e < EE) {
        int pos = atomicAdd(&d_cursor[dst[e]], 1);
        d_epack[pos] = (d_iperm[src[e]] << 2) | et[e];
    }
}

// ---------------- weight pack: fp32 -> transposed bf16 hi/lo -------------------
// plain layout per chunk: [n][k] halves (n = output col, k contiguous).
// chunk c<6: adapt type t=c/2, k-half (c&1). chunks 6..29: layer l, gemm g(k,q,v,a), type t.
__global__ void k_wprep(const float* __restrict__ Wad, const float* __restrict__ Wk,
                        const float* __restrict__ Wq, const float* __restrict__ Wv,
                        const float* __restrict__ Wa) {
    int c = blockIdx.x;
    const float* W; int k0 = 0;
    if (c < 6) {
        int t = c >> 1; k0 = (c & 1) * 128;
        W = Wad + (size_t)t * 256 * 128;
    } else {
        int cc = c - 6;
        int l = cc / 12, rem = cc % 12, g = rem / 3, t = rem % 3;
        const float* Wg = (g == 0) ? Wk : (g == 1) ? Wq : (g == 2) ? Wv : Wa;
        W = Wg + (size_t)l * 3 * 128 * 128 + (size_t)t * 128 * 128;
    }
    __nv_bfloat16* oh = d_wpack_hi + (size_t)c * 16384;
    __nv_bfloat16* ol = d_wpack_lo + (size_t)c * 16384;
    for (int i = threadIdx.x; i < 16384; i += 256) {
        int n = i >> 7, k = i & 127;          // out[n][k] = W[k0+k][n]
        float v = W[(size_t)(k0 + k) * 128 + n];
        __nv_bfloat16 h = __float2bfloat16(v);
        oh[i] = h;
        ol[i] = __float2bfloat16(v - __bfloat162float(h));
    }
}

// ---------------- HMMA GEMM ----------------------------------------------------
// out[p] = ACT( A[p] @ W_t + b_t ), tile M=128, N=128, K = nch*128, bf16 3-term.
// GATHER: 0 = A contiguous [NP][nch*128]; 1 = gather rows of A via nperm;
//         2 = A contiguous + GELU applied during conversion.
// smem (halves, row stride 136 = 128 + 8 pad):
#define SROW   136
#define OFF_AH 0
#define OFF_AL 34816
#define OFF_BH 69632
#define OFF_BL 104448
#define GSMEM  139264

__device__ __forceinline__ float* pick_out(int c) {
    switch (c) { case 0: return d_h0; case 1: return d_kb; case 2: return d_qb;
                 case 3: return d_vb; case 4: return d_trans; }
    return d_h0;
}

template<int GATHER, int ACT>
__global__ void __launch_bounds__(256)
k_gemm(const float* __restrict__ Aext, int in_code, int out_code, int nch, int cbase,
       const float* __restrict__ bias) {
    extern __shared__ char smem[];
    const uint32_t sb = smem_u32(smem);
    const int tid = threadIdx.x;
    const int wid = tid >> 5, lane = tid & 31;
    const int base = blockIdx.x * 128;
    const int t = (base >= d_topad[1]) + (base >= d_topad[2]);

    const float* A = Aext;
    if (GATHER != 1) A = (in_code == 0) ? d_h0 : (in_code == 1) ? d_h1 : d_agg;
    float* outp = pick_out(out_code);
    const float* bt = bias + t * 128;
    const int lda = nch * 128;

    const int wm = wid & 3, wn = wid >> 2;

    float acc[2][8][4];
    #pragma unroll
    for (int mi = 0; mi < 2; mi++)
        #pragma unroll
        for (int nj = 0; nj < 8; nj++)
            #pragma unroll
            for (int e = 0; e < 4; e++) acc[mi][nj][e] = 0.f;

    // per-lane ldmatrix base addresses (byte offsets within smem buffers)
    const uint32_t aoff = (uint32_t)((wm*32 + (lane & 15)) * SROW + (lane >> 4) * 8) * 2;
    const int l16 = lane & 15;
    const uint32_t boff = (uint32_t)((wn*64 + (l16 & 7)) * SROW + (l16 >> 3) * 8) * 2;

    for (int kc = 0; kc < nch; kc++) {
        if (kc > 0) __syncthreads();
        // B copy from prepacked gmem -> padded smem rows
        {
            int chunk = cbase + t * nch + kc;
            const uint4* bh = (const uint4*)(d_wpack_hi + (size_t)chunk * 16384);
            const uint4* bl = (const uint4*)(d_wpack_lo + (size_t)chunk * 16384);
            #pragma unroll
            for (int i = 0; i < 8; i++) {
                int idx = tid + i * 256;          // 2048 uint4 granules
                int n = idx >> 4, k8g = idx & 15;
                uint32_t doff = (uint32_t)(n * SROW + k8g * 8) * 2;
                *(uint4*)(smem + OFF_BH + doff) = bh[idx];
                *(uint4*)(smem + OFF_BL + doff) = bl[idx];
            }
        }
        // A load + fp32->bf16 hi/lo split
        #pragma unroll
        for (int i = 0; i < 8; i++) {
            int gi = tid + i * 256;               // 2048 granules of 8 elems
            int row = gi >> 4;
            int k8 = (gi & 15) * 8;
            float v[8];
            if (GATHER == 1) {
                int rn = d_nperm[base + row];
                if (rn >= 0) {
                    const float4* ap = (const float4*)(A + (size_t)rn * lda + kc*128 + k8);
                    float4 a0 = ap[0], a1 = ap[1];
                    v[0]=a0.x; v[1]=a0.y; v[2]=a0.z; v[3]=a0.w;
                    v[4]=a1.x; v[5]=a1.y; v[6]=a1.z; v[7]=a1.w;
                } else {
                    #pragma unroll
                    for (int j = 0; j < 8; j++) v[j] = 0.f;
                }
            } else {
                const float4* ap = (const float4*)(A + (size_t)(base + row) * lda + kc*128 + k8);
                float4 a0 = ap[0], a1 = ap[1];
                v[0]=a0.x; v[1]=a0.y; v[2]=a0.z; v[3]=a0.w;
                v[4]=a1.x; v[5]=a1.y; v[6]=a1.z; v[7]=a1.w;
                if (GATHER == 2) {
                    #pragma unroll
                    for (int j = 0; j < 8; j++)
                        v[j] = 0.5f * v[j] * (1.0f + erff(v[j] * 0.70710678118654752f));
                }
            }
            union { __nv_bfloat16 b[8]; uint4 u; } ph, pl;
            #pragma unroll
            for (int j = 0; j < 8; j++) {
                __nv_bfloat16 h = __float2bfloat16(v[j]);
                ph.b[j] = h;
                pl.b[j] = __float2bfloat16(v[j] - __bfloat162float(h));
            }
            uint32_t doff = (uint32_t)(row * SROW + k8) * 2;
            *(uint4*)(smem + OFF_AH + doff) = ph.u;
            *(uint4*)(smem + OFF_AL + doff) = pl.u;
        }
        __syncthreads();

        #pragma unroll
        for (int ks = 0; ks < 8; ks++) {
            uint32_t ah[2][4], al[2][4];
            #pragma unroll
            for (int mi = 0; mi < 2; mi++) {
                uint32_t ad = sb + aoff + (uint32_t)(mi*16*SROW + ks*16) * 2;
                ldmatrix_x4(ah[mi], ad + OFF_AH);
                ldmatrix_x4(al[mi], ad + OFF_AL);
            }
            uint32_t bh[8][2], bl[8][2];
            #pragma unroll
            for (int nj = 0; nj < 8; nj++) {
                uint32_t bd = sb + boff + (uint32_t)(nj*8*SROW + ks*16) * 2;
                ldmatrix_x2(bh[nj], bd + OFF_BH);
                ldmatrix_x2(bl[nj], bd + OFF_BL);
            }
            #pragma unroll
            for (int mi = 0; mi < 2; mi++)
                #pragma unroll
                for (int nj = 0; nj < 8; nj++) {
                    mma16816(acc[mi][nj], ah[mi], bh[nj]);
                    mma16816(acc[mi][nj], ah[mi], bl[nj]);
                    mma16816(acc[mi][nj], al[mi], bh[nj]);
                }
        }
    }
    __syncthreads();   // all ldmatrix reads done before stage overlays A smem

    // epilogue: regs -> (bias, act) -> smem stage -> coalesced gmem
    float* stage = (float*)smem;              // [128][132]
    #pragma unroll
    for (int mi = 0; mi < 2; mi++) {
        #pragma unroll
        for (int nj = 0; nj < 8; nj++) {
            int row = wm*32 + mi*16 + (lane >> 2);
            int col = wn*64 + nj*8 + 2*(lane & 3);
            float b0 = __ldg(&bt[col]), b1 = __ldg(&bt[col+1]);
            float v0 = acc[mi][nj][0] + b0;
            float v1 = acc[mi][nj][1] + b1;
            float v2 = acc[mi][nj][2] + b0;
            float v3 = acc[mi][nj][3] + b1;
            if (ACT == 1) { v0 = tanhf(v0); v1 = tanhf(v1); v2 = tanhf(v2); v3 = tanhf(v3); }
            stage[row*132 + col]     = v0;
            stage[row*132 + col + 1] = v1;
            stage[(row+8)*132 + col]     = v2;
            stage[(row+8)*132 + col + 1] = v3;
        }
    }
    __syncthreads();
    for (int i = tid; i < 4096; i += 256) {
        int row = i >> 5, c4 = i & 31;
        *(float4*)(outp + ((size_t)(base + row)) * 128 + c4 * 4) =
            *(const float4*)(stage + row * 132 + c4 * 4);
    }
}

// ---------------- per-node relation transforms (permuted layout) ---------------
__global__ void k_reltrans(const float* __restrict__ Ratt, const float* __restrict__ Rmsg) {
    const int slot = blockIdx.y;
    const int r = slot >> 1;
    const bool isV = slot & 1;
    const float* srcv = isV ? d_vb : d_kb;
    float* dstv = isV ? d_vrel : d_krel;
    const float* Wh = (isV ? Rmsg : Ratt) + r*HH*DKK*DKK;

    const int lane = threadIdx.x & 31;
    const int wid  = threadIdx.x >> 5;
    const int h = lane >> 2;
    const int f0 = (lane & 3) * 4;
    const float* Wp = Wh + h*256;

    float4 w[16];
    #pragma unroll
    for (int d = 0; d < 16; d++) w[d] = *(const float4*)(Wp + d*16 + f0);

    const int wpb = blockDim.x >> 5;
    for (int n = blockIdx.x*wpb + wid; n < NP; n += gridDim.x*wpb) {
        const float4* row = (const float4*)(srcv + (size_t)n*128) + h*4;
        float4 q0 = row[0], q1 = row[1], q2 = row[2], q3 = row[3];
        float4 acc = make_float4(0.f,0.f,0.f,0.f);
        #define RMAC(qc, d) acc.x=fmaf(qc,w[d].x,acc.x); acc.y=fmaf(qc,w[d].y,acc.y); \
                            acc.z=fmaf(qc,w[d].z,acc.z); acc.w=fmaf(qc,w[d].w,acc.w);
        RMAC(q0.x,0)  RMAC(q0.y,1)  RMAC(q0.z,2)  RMAC(q0.w,3)
        RMAC(q1.x,4)  RMAC(q1.y,5)  RMAC(q1.z,6)  RMAC(q1.w,7)
        RMAC(q2.x,8)  RMAC(q2.y,9)  RMAC(q2.z,10) RMAC(q2.w,11)
        RMAC(q3.x,12) RMAC(q3.y,13) RMAC(q3.z,14) RMAC(q3.w,15)
        #undef RMAC
        ((float4*)dstv)[((size_t)n*RR + r)*32 + lane] = acc;
    }
}

// ---------------- edge phase: warp-per-dst, online softmax ---------------------
__global__ void k_edge(const float* __restrict__ pri) {
    const int n = (blockIdx.x*blockDim.x + threadIdx.x) >> 5;
    if (n >= NN) return;
    const int lane = threadIdx.x & 31;
    const int grp = lane >> 2;
    const unsigned full = 0xffffffffu;

    const int ip = d_iperm[n];
    float4 q4 = ((const float4*)d_qb)[(size_t)ip*32 + lane];
    const int beg = d_off[n], end = d_off[n+1];

    float m = -1e30f, s = 0.f;
    float4 acc = make_float4(0.f,0.f,0.f,0.f);

    for (int e = beg; e < end; e++) {
        int pk = d_epack[e];
        int sp = pk >> 2;
        int r  = pk & 3;
        size_t bidx = ((size_t)sp*RR + r)*32 + lane;
        float4 k4 = ((const float4*)d_krel)[bidx];
        float4 v4 = ((const float4*)d_vrel)[bidx];
        float p = q4.x*k4.x + q4.y*k4.y + q4.z*k4.z + q4.w*k4.w;
        p += __shfl_xor_sync(full, p, 1);
        p += __shfl_xor_sync(full, p, 2);
        float l = p * __ldg(&pri[r*HH + grp]) * 0.25f;
        float mn = fmaxf(m, l);
        float corr = __expf(m - mn);
        float w = __expf(l - mn);
        s = s*corr + w;
        acc.x = fmaf(w, v4.x, acc.x*corr);
        acc.y = fmaf(w, v4.y, acc.y*corr);
        acc.z = fmaf(w, v4.z, acc.z*corr);
        acc.w = fmaf(w, v4.w, acc.w*corr);
        m = mn;
    }
    float inv = 1.0f / fmaxf(s, 1e-9f);
    acc.x *= inv; acc.y *= inv; acc.z *= inv; acc.w *= inv;
    ((float4*)d_agg)[(size_t)ip*32 + lane] = acc;
}

// ---------------- combine ------------------------------------------------------
__global__ void k_combine1(const float* __restrict__ skip,
                           const float* __restrict__ gamma,
                           const float* __restrict__ beta) {
    const int p = (blockIdx.x*blockDim.x + threadIdx.x) >> 5;
    if (p >= NP) return;
    const int lane = threadIdx.x & 31;
    const unsigned full = 0xffffffffu;
    int t = (p >= d_topad[1]) + (p >= d_topad[2]);
    float alpha = 1.0f / (1.0f + __expf(-skip[t]));
    float4 tr = ((const float4*)d_trans)[(size_t)p*32 + lane];
    float4 hx = ((const float4*)d_h0)[(size_t)p*32 + lane];
    float ia = 1.0f - alpha;
    float4 o;
    o.x = tr.x*alpha + hx.x*ia;
    o.y = tr.y*alpha + hx.y*ia;
    o.z = tr.z*alpha + hx.z*ia;
    o.w = tr.w*alpha + hx.w*ia;
    float sm = o.x + o.y + o.z + o.w;
    float sq = o.x*o.x + o.y*o.y + o.z*o.z + o.w*o.w;
    #pragma unroll
    for (int d = 16; d; d >>= 1) {
        sm += __shfl_xor_sync(full, sm, d);
        sq += __shfl_xor_sync(full, sq, d);
    }
    float mean = sm * (1.0f/128.0f);
    float var  = sq * (1.0f/128.0f) - mean*mean;
    float rstd = rsqrtf(var + 1e-5f);
    float4 g4 = ((const float4*)gamma)[t*32 + lane];
    float4 b4 = ((const float4*)beta)[t*32 + lane];
    float4 y;
    y.x = fmaxf((o.x-mean)*rstd*g4.x + b4.x, 0.f);
    y.y = fmaxf((o.y-mean)*rstd*g4.y + b4.y, 0.f);
    y.z = fmaxf((o.z-mean)*rstd*g4.z + b4.z, 0.f);
    y.w = fmaxf((o.w-mean)*rstd*g4.w + b4.w, 0.f);
    ((float4*)d_h1)[(size_t)p*32 + lane] = y;
}

__global__ void k_combine2(const float* __restrict__ skip, float* __restrict__ out) {
    const int p = (blockIdx.x*blockDim.x + threadIdx.x) >> 5;
    if (p >= NP) return;
    const int lane = threadIdx.x & 31;
    int node = d_nperm[p];
    if (node < 0) return;
    int t = (p >= d_topad[1]) + (p >= d_topad[2]);
    float alpha = 1.0f / (1.0f + __expf(-skip[t]));
    float ia = 1.0f - alpha;
    float4 tr = ((const float4*)d_trans)[(size_t)p*32 + lane];
    float4 hx = ((const float4*)d_h1)[(size_t)p*32 + lane];
    float4 o;
    o.x = tr.x*alpha + hx.x*ia;
    o.y = tr.y*alpha + hx.y*ia;
    o.z = tr.z*alpha + hx.z*ia;
    o.w = tr.w*alpha + hx.w*ia;
    ((float4*)(out + (size_t)node*128))[lane] = o;
}

// ---------------- launch --------------------------------------------------------
extern "C" void kernel_launch(void* const* d_in, const int* in_sizes, int n_in,
                              void* d_out, int out_size) {
    const float* x      = (const float*)d_in[0];
    const int*   ntypes = (const int*)d_in[1];
    const int*   ei     = (const int*)d_in[2];
    const int*   et     = (const int*)d_in[3];
    const float* Wad    = (const float*)d_in[4];
    const float* bad    = (const float*)d_in[5];
    const float* Wk     = (const float*)d_in[6];
    const float* bk     = (const float*)d_in[7];
    const float* Wq     = (const float*)d_in[8];
    const float* bq     = (const float*)d_in[9];
    const float* Wv     = (const float*)d_in[10];
    const float* bv     = (const float*)d_in[11];
    const float* Wa     = (const float*)d_in[12];
    const float* ba     = (const float*)d_in[13];
    const float* pri    = (const float*)d_in[14];
    const float* ratt   = (const float*)d_in[15];
    const float* rmsg   = (const float*)d_in[16];
    const float* skip   = (const float*)d_in[17];
    const float* gamma  = (const float*)d_in[18];
    const float* beta   = (const float*)d_in[19];
    float* out = (float*)d_out;

    const int* srcA = ei;
    const int* dstA = ei + EE;

    cudaFuncSetAttribute(k_gemm<1,1>, cudaFuncAttributeMaxDynamicSharedMemorySize, GSMEM);
    cudaFuncSetAttribute(k_gemm<0,0>, cudaFuncAttributeMaxDynamicSharedMemorySize, GSMEM);
    cudaFuncSetAttribute(k_gemm<2,0>, cudaFuncAttributeMaxDynamicSharedMemorySize, GSMEM);

    const int SCAN_BLK = (NN + 255) / 256;
    const int WARP_BLK = (NN*32 + 255) / 256;
    const int PWARP_BLK = NP*32 / 256;

    k_init<<<(NP+255)/256, 256>>>();
    k_count<<<(EE+255)/256, 256>>>(ntypes, dstA);
    k_toffsets<<<1, 1>>>();
    k_scatter_nodes<<<(NN+255)/256, 256>>>(ntypes);
    k_scan1<<<SCAN_BLK, 256>>>();
    k_scan2<<<1, 256>>>(SCAN_BLK);
    k_scan3<<<SCAN_BLK, 256>>>();
    k_scatter_edges<<<(EE+255)/256, 256>>>(srcA, dstA, et);
    k_wprep<<<NCHUNKS, 256>>>(Wad, Wk, Wq, Wv, Wa);

    // adapt: h0 = tanh(typed_linear(x)); gather rows of x via nperm
    k_gemm<1,1><<<NTILE, 256, GSMEM>>>(x, -1, 0, 2, 0, bad);

    const int LB = TT*HIDD;
    const int LP = RR*HH;
    const int LR = RR*HH*DKK*DKK;

    for (int l = 0; l < 2; l++) {
        int in_code = l;   // 0 -> d_h0, 1 -> d_h1
        int cb = 6 + l*12;
        k_gemm<0,0><<<NTILE, 256, GSMEM>>>(nullptr, in_code, 1, 1, cb + 0, bk + l*LB);
        k_gemm<0,0><<<NTILE, 256, GSMEM>>>(nullptr, in_code, 2, 1, cb + 3, bq + l*LB);
        k_gemm<0,0><<<NTILE, 256, GSMEM>>>(nullptr, in_code, 3, 1, cb + 6, bv + l*LB);
        k_reltrans<<<dim3(296, 8), 256>>>(ratt + (size_t)l*LR, rmsg + (size_t)l*LR);
        k_edge<<<WARP_BLK, 256>>>(pri + l*LP);
        k_gemm<2,0><<<NTILE, 256, GSMEM>>>(nullptr, 2, 4, 1, cb + 9, ba + l*LB);
        if (l == 0) {
            k_combine1<<<PWARP_BLK, 256>>>(skip + l*TT, gamma, beta);
        } else {
            k_combine2<<<PWARP_BLK, 256>>>(skip + l*TT, out);
        }
    }
}

// round 5
// speedup vs baseline: 1.8991x; 1.4605x over previous
#include <cuda_runtime.h>
#include <cuda_bf16.h>
#include <cuda_fp16.h>
#include <cstdint>
#include <math.h>

#define NN   50000
#define EE   400000
#define IND  256
#define HIDD 128
#define TT   3
#define RR   4
#define HH   8
#define DKK  16
#define NP   50432          // 394 blocks * 128
#define NTILE 394
#define NCHUNKS 30          // weight pack chunks

// ---------------- scratch (static device globals) -----------------------------
__device__ float d_h0[NP*HIDD];
__device__ float d_h1[NP*HIDD];
__device__ float d_agg[NP*HIDD];
__device__ float d_trans[NP*HIDD];
__device__ __half d_kh[NP*HIDD];
__device__ __half d_qh[NP*HIDD];
__device__ __half d_vh[NP*HIDD];
__device__ __half d_kvrel[(size_t)NP*RR*256];   // [p*4+r][0:128]=krel*pri/4, [128:256]=vrel
__device__ __nv_bfloat16 d_wpack_hi[NCHUNKS*16384];
__device__ __nv_bfloat16 d_wpack_lo[NCHUNKS*16384];
__device__ int   d_deg[NN];
__device__ int   d_off[NN+1];
__device__ int   d_cursor[NN];
__device__ int   d_epack[EE];
__device__ int   d_bsum[256];
__device__ int   d_bpre[256];
__device__ int   d_tcnt[TT];
__device__ int   d_topad[TT+1];
__device__ int   d_tcur[TT];
__device__ int   d_nperm[NP];
__device__ int   d_iperm[NN];

// ---------------- helpers -------------------------------------------------------
__device__ __forceinline__ uint32_t smem_u32(const void* p) {
    uint32_t a;
    asm("{ .reg .u64 t; cvta.to.shared.u64 t, %1; cvt.u32.u64 %0, t; }" : "=r"(a) : "l"(p));
    return a;
}
__device__ __forceinline__ void ldmatrix_x4(uint32_t* r, uint32_t addr) {
    asm volatile("ldmatrix.sync.aligned.m8n8.x4.shared.b16 {%0,%1,%2,%3}, [%4];"
                 : "=r"(r[0]), "=r"(r[1]), "=r"(r[2]), "=r"(r[3]) : "r"(addr));
}
__device__ __forceinline__ void ldmatrix_x2(uint32_t* r, uint32_t addr) {
    asm volatile("ldmatrix.sync.aligned.m8n8.x2.shared.b16 {%0,%1}, [%2];"
                 : "=r"(r[0]), "=r"(r[1]) : "r"(addr));
}
__device__ __forceinline__ void mma16816(float* d, const uint32_t* a, const uint32_t* b) {
    asm volatile("mma.sync.aligned.m16n8k16.row.col.f32.bf16.bf16.f32 "
                 "{%0,%1,%2,%3}, {%4,%5,%6,%7}, {%8,%9}, {%0,%1,%2,%3};"
                 : "+f"(d[0]), "+f"(d[1]), "+f"(d[2]), "+f"(d[3])
                 : "r"(a[0]), "r"(a[1]), "r"(a[2]), "r"(a[3]), "r"(b[0]), "r"(b[1]));
}
__device__ __forceinline__ float4 h4_to_f4(uint2 u) {
    __half2 a = *reinterpret_cast<__half2*>(&u.x);
    __half2 b = *reinterpret_cast<__half2*>(&u.y);
    float2 fa = __half22float2(a), fb = __half22float2(b);
    return make_float4(fa.x, fa.y, fb.x, fb.y);
}
__device__ __forceinline__ uint2 f4_to_h4(float4 f) {
    __half2 a = __floats2half2_rn(f.x, f.y);
    __half2 b = __floats2half2_rn(f.z, f.w);
    uint2 u;
    u.x = *reinterpret_cast<uint32_t*>(&a);
    u.y = *reinterpret_cast<uint32_t*>(&b);
    return u;
}

// ---------------- setup kernels ------------------------------------------------
__global__ void k_init() {
    int i = blockIdx.x*blockDim.x + threadIdx.x;
    if (i < NP) d_nperm[i] = -1;
    if (i < NN) d_deg[i] = 0;
    if (i < TT) d_tcnt[i] = 0;
}
__global__ void k_count(const int* __restrict__ ntypes, const int* __restrict__ dst) {
    __shared__ int sh[TT];
    if (threadIdx.x < TT) sh[threadIdx.x] = 0;
    __syncthreads();
    int i = blockIdx.x*blockDim.x + threadIdx.x;
    if (i < NN) atomicAdd(&sh[ntypes[i]], 1);
    if (i < EE) atomicAdd(&d_deg[dst[i]], 1);
    __syncthreads();
    if (threadIdx.x < TT && sh[threadIdx.x]) atomicAdd(&d_tcnt[threadIdx.x], sh[threadIdx.x]);
}
__global__ void k_toffsets() {
    int run = 0;
    for (int t = 0; t < TT; t++) {
        d_topad[t] = run; d_tcur[t] = run;
        run += ((d_tcnt[t] + 127) / 128) * 128;
    }
    d_topad[TT] = run;
}
__global__ void k_scatter_nodes(const int* __restrict__ ntypes) {
    __shared__ int scnt[TT], sbase[TT];
    if (threadIdx.x < TT) scnt[threadIdx.x] = 0;
    __syncthreads();
    int i = blockIdx.x*blockDim.x + threadIdx.x;
    int t = 0, myidx = 0;
    bool valid = (i < NN);
    if (valid) { t = ntypes[i]; myidx = atomicAdd(&scnt[t], 1); }
    __syncthreads();
    if (threadIdx.x < TT) sbase[threadIdx.x] = atomicAdd(&d_tcur[threadIdx.x], scnt[threadIdx.x]);
    __syncthreads();
    if (valid) {
        int p = sbase[t] + myidx;
        d_nperm[p] = i;
        d_iperm[i] = p;
    }
}
__device__ __forceinline__ int block_scan_incl(int x, int* wsum) {
    unsigned full = 0xffffffffu;
    int lane = threadIdx.x & 31, wid = threadIdx.x >> 5;
    int v = x;
    #pragma unroll
    for (int d = 1; d < 32; d <<= 1) {
        int t = __shfl_up_sync(full, v, d);
        if (lane >= d) v += t;
    }
    if (lane == 31) wsum[wid] = v;
    __syncthreads();
    if (threadIdx.x == 0) {
        int run = 0;
        #pragma unroll
        for (int w = 0; w < 8; w++) { int t = wsum[w]; wsum[w] = run; run += t; }
    }
    __syncthreads();
    return v + wsum[wid];
}
__global__ void k_scan1() {
    __shared__ int wsum[8];
    int i = blockIdx.x*256 + threadIdx.x;
    int x = (i < NN) ? d_deg[i] : 0;
    int inc = block_scan_incl(x, wsum);
    if (i < NN) d_off[i] = inc - x;
    if (threadIdx.x == 255) d_bsum[blockIdx.x] = inc;
}
__global__ void k_scan2(int nblocks) {
    __shared__ int wsum[8];
    int t = threadIdx.x;
    int x = (t < nblocks) ? d_bsum[t] : 0;
    int inc = block_scan_incl(x, wsum);
    d_bpre[t] = inc - x;
}
__global__ void k_scan3() {
    int i = blockIdx.x*256 + threadIdx.x;
    if (i < NN) {
        int v = d_off[i] + d_bpre[i >> 8];
        d_off[i] = v; d_cursor[i] = v;
    }
    if (i == 0) d_off[NN] = EE;
}
__global__ void k_scatter_edges(const int* __restrict__ src, const int* __restrict__ dst,
                                const int* __restrict__ et) {
    int e = blockIdx.x*blockDim.x + threadIdx.x;
    if (e < EE) {
        int pos = atomicAdd(&d_cursor[dst[e]], 1);
        d_epack[pos] = (d_iperm[src[e]] << 2) | et[e];
    }
}

// ---------------- weight pack: fp32 -> transposed bf16 hi/lo -------------------
__global__ void k_wprep(const float* __restrict__ Wad, const float* __restrict__ Wk,
                        const float* __restrict__ Wq, const float* __restrict__ Wv,
                        const float* __restrict__ Wa) {
    int c = blockIdx.x;
    const float* W; int k0 = 0;
    if (c < 6) {
        int t = c >> 1; k0 = (c & 1) * 128;
        W = Wad + (size_t)t * 256 * 128;
    } else {
        int cc = c - 6;
        int l = cc / 12, rem = cc % 12, g = rem / 3, t = rem % 3;
        const float* Wg = (g == 0) ? Wk : (g == 1) ? Wq : (g == 2) ? Wv : Wa;
        W = Wg + (size_t)l * 3 * 128 * 128 + (size_t)t * 128 * 128;
    }
    __nv_bfloat16* oh = d_wpack_hi + (size_t)c * 16384;
    __nv_bfloat16* ol = d_wpack_lo + (size_t)c * 16384;
    for (int i = threadIdx.x; i < 16384; i += 256) {
        int n = i >> 7, k = i & 127;
        float v = W[(size_t)(k0 + k) * 128 + n];
        __nv_bfloat16 h = __float2bfloat16(v);
        oh[i] = h;
        ol[i] = __float2bfloat16(v - __bfloat162float(h));
    }
}

// ---------------- HMMA GEMM core ------------------------------------------------
#define SROW   136
#define OFF_AH 0
#define OFF_AL 34816
#define OFF_BH 69632
#define OFF_BL 104448
#define GSMEM  139264

template<int GATHER, int ACT, int OUTH>
__device__ __forceinline__ void gemm_core(const float* __restrict__ A, int nch, int cbase,
                                          const float* __restrict__ bias,
                                          float* __restrict__ outf, __half* __restrict__ outh) {
    extern __shared__ char smem[];
    const uint32_t sb = smem_u32(smem);
    const int tid = threadIdx.x;
    const int wid = tid >> 5, lane = tid & 31;
    const int base = blockIdx.x * 128;
    const int t = (base >= d_topad[1]) + (base >= d_topad[2]);
    const float* bt = bias + t * 128;
    const int lda = nch * 128;
    const int wm = wid & 3, wn = wid >> 2;

    float acc[2][8][4];
    #pragma unroll
    for (int mi = 0; mi < 2; mi++)
        #pragma unroll
        for (int nj = 0; nj < 8; nj++)
            #pragma unroll
            for (int e = 0; e < 4; e++) acc[mi][nj][e] = 0.f;

    const uint32_t aoff = (uint32_t)((wm*32 + (lane & 15)) * SROW + (lane >> 4) * 8) * 2;
    const int l16 = lane & 15;
    const uint32_t boff = (uint32_t)((wn*64 + (l16 & 7)) * SROW + (l16 >> 3) * 8) * 2;

    for (int kc = 0; kc < nch; kc++) {
        if (kc > 0) __syncthreads();
        {
            int chunk = cbase + t * nch + kc;
            const uint4* bh = (const uint4*)(d_wpack_hi + (size_t)chunk * 16384);
            const uint4* bl = (const uint4*)(d_wpack_lo + (size_t)chunk * 16384);
            #pragma unroll
            for (int i = 0; i < 8; i++) {
                int idx = tid + i * 256;
                int n = idx >> 4, k8g = idx & 15;
                uint32_t doff = (uint32_t)(n * SROW + k8g * 8) * 2;
                *(uint4*)(smem + OFF_BH + doff) = bh[idx];
                *(uint4*)(smem + OFF_BL + doff) = bl[idx];
            }
        }
        #pragma unroll
        for (int i = 0; i < 8; i++) {
            int gi = tid + i * 256;
            int row = gi >> 4;
            int k8 = (gi & 15) * 8;
            float v[8];
            if (GATHER == 1) {
                int rn = d_nperm[base + row];
                if (rn >= 0) {
                    const float4* ap = (const float4*)(A + (size_t)rn * lda + kc*128 + k8);
                    float4 a0 = ap[0], a1 = ap[1];
                    v[0]=a0.x; v[1]=a0.y; v[2]=a0.z; v[3]=a0.w;
                    v[4]=a1.x; v[5]=a1.y; v[6]=a1.z; v[7]=a1.w;
                } else {
                    #pragma unroll
                    for (int j = 0; j < 8; j++) v[j] = 0.f;
                }
            } else {
                const float4* ap = (const float4*)(A + (size_t)(base + row) * lda + kc*128 + k8);
                float4 a0 = ap[0], a1 = ap[1];
                v[0]=a0.x; v[1]=a0.y; v[2]=a0.z; v[3]=a0.w;
                v[4]=a1.x; v[5]=a1.y; v[6]=a1.z; v[7]=a1.w;
                if (GATHER == 2) {
                    #pragma unroll
                    for (int j = 0; j < 8; j++)
                        v[j] = 0.5f * v[j] * (1.0f + erff(v[j] * 0.70710678118654752f));
                }
            }
            union { __nv_bfloat16 b[8]; uint4 u; } ph, pl;
            #pragma unroll
            for (int j = 0; j < 8; j++) {
                __nv_bfloat16 h = __float2bfloat16(v[j]);
                ph.b[j] = h;
                pl.b[j] = __float2bfloat16(v[j] - __bfloat162float(h));
            }
            uint32_t doff = (uint32_t)(row * SROW + k8) * 2;
            *(uint4*)(smem + OFF_AH + doff) = ph.u;
            *(uint4*)(smem + OFF_AL + doff) = pl.u;
        }
        __syncthreads();

        #pragma unroll
        for (int ks = 0; ks < 8; ks++) {
            uint32_t ah[2][4], al[2][4];
            #pragma unroll
            for (int mi = 0; mi < 2; mi++) {
                uint32_t ad = sb + aoff + (uint32_t)(mi*16*SROW + ks*16) * 2;
                ldmatrix_x4(ah[mi], ad + OFF_AH);
                ldmatrix_x4(al[mi], ad + OFF_AL);
            }
            uint32_t bhf[8][2], blf[8][2];
            #pragma unroll
            for (int nj = 0; nj < 8; nj++) {
                uint32_t bd = sb + boff + (uint32_t)(nj*8*SROW + ks*16) * 2;
                ldmatrix_x2(bhf[nj], bd + OFF_BH);
                ldmatrix_x2(blf[nj], bd + OFF_BL);
            }
            #pragma unroll
            for (int mi = 0; mi < 2; mi++)
                #pragma unroll
                for (int nj = 0; nj < 8; nj++) {
                    mma16816(acc[mi][nj], ah[mi], bhf[nj]);
                    mma16816(acc[mi][nj], ah[mi], blf[nj]);
                    mma16816(acc[mi][nj], al[mi], bhf[nj]);
                }
        }
    }
    __syncthreads();

    float* stage = (float*)smem;              // [128][132]
    #pragma unroll
    for (int mi = 0; mi < 2; mi++) {
        #pragma unroll
        for (int nj = 0; nj < 8; nj++) {
            int row = wm*32 + mi*16 + (lane >> 2);
            int col = wn*64 + nj*8 + 2*(lane & 3);
            float b0 = __ldg(&bt[col]), b1 = __ldg(&bt[col+1]);
            float v0 = acc[mi][nj][0] + b0;
            float v1 = acc[mi][nj][1] + b1;
            float v2 = acc[mi][nj][2] + b0;
            float v3 = acc[mi][nj][3] + b1;
            if (ACT == 1) { v0 = tanhf(v0); v1 = tanhf(v1); v2 = tanhf(v2); v3 = tanhf(v3); }
            stage[row*132 + col]     = v0;
            stage[row*132 + col + 1] = v1;
            stage[(row+8)*132 + col]     = v2;
            stage[(row+8)*132 + col + 1] = v3;
        }
    }
    __syncthreads();
    if (OUTH) {
        for (int i = tid; i < 4096; i += 256) {
            int row = i >> 5, c4 = i & 31;
            float4 f = *(const float4*)(stage + row * 132 + c4 * 4);
            *(uint2*)(outh + (size_t)(base + row) * 128 + c4 * 4) = f4_to_h4(f);
        }
    } else {
        for (int i = tid; i < 4096; i += 256) {
            int row = i >> 5, c4 = i & 31;
            *(float4*)(outf + ((size_t)(base + row)) * 128 + c4 * 4) =
                *(const float4*)(stage + row * 132 + c4 * 4);
        }
    }
}

__global__ void __launch_bounds__(256)
k_gemm_adapt(const float* __restrict__ x, const float* __restrict__ bad) {
    gemm_core<1,1,0>(x, 2, 0, bad, d_h0, nullptr);
}
__global__ void __launch_bounds__(256)
k_gemm_kqv(int in_code, int cb, const float* __restrict__ bk,
           const float* __restrict__ bq, const float* __restrict__ bv) {
    const float* A = in_code ? d_h1 : d_h0;
    int g = blockIdx.y;
    __half* oh = (g == 0) ? d_kh : (g == 1) ? d_qh : d_vh;
    const float* bi = (g == 0) ? bk : (g == 1) ? bq : bv;
    gemm_core<0,0,1>(A, 1, cb + g*3, bi, nullptr, oh);
}
__global__ void __launch_bounds__(256)
k_gemm_att(int cb9, const float* __restrict__ ba) {
    gemm_core<2,0,0>(d_agg, 1, cb9, ba, d_trans, nullptr);
}

// ---------------- per-node relation transforms (fp16 in/out) -------------------
__global__ void k_reltrans(const float* __restrict__ Ratt, const float* __restrict__ Rmsg,
                           const float* __restrict__ pri) {
    const int slot = blockIdx.y;
    const int r = slot >> 1;
    const bool isV = slot & 1;
    const __half* srcv = isV ? d_vh : d_kh;
    const float* Wh = (isV ? Rmsg : Ratt) + r*HH*DKK*DKK;

    const int lane = threadIdx.x & 31;
    const int wid  = threadIdx.x >> 5;
    const int h = lane >> 2;
    const int f0 = (lane & 3) * 4;
    const float* Wp = Wh + h*256;
    const float pscale = isV ? 1.0f : (__ldg(&pri[r*HH + h]) * 0.25f);

    float4 w[16];
    #pragma unroll
    for (int d = 0; d < 16; d++) w[d] = *(const float4*)(Wp + d*16 + f0);

    const int wpb = blockDim.x >> 5;
    for (int n = blockIdx.x*wpb + wid; n < NP; n += gridDim.x*wpb) {
        // head h input = 16 halves = 32 bytes = two uint4 loads
        uint4 raw0 = *(const uint4*)(srcv + (size_t)n*128 + h*16);
        uint4 raw1 = *(const uint4*)(srcv + (size_t)n*128 + h*16 + 8);
        float f[16];
        {
            const __half2* hp0 = reinterpret_cast<const __half2*>(&raw0);
            const __half2* hp1 = reinterpret_cast<const __half2*>(&raw1);
            #pragma unroll
            for (int j = 0; j < 4; j++) {
                float2 t2 = __half22float2(hp0[j]);
                f[2*j] = t2.x; f[2*j+1] = t2.y;
                float2 u2 = __half22float2(hp1[j]);
                f[8+2*j] = u2.x; f[8+2*j+1] = u2.y;
            }
        }
        float4 acc = make_float4(0.f,0.f,0.f,0.f);
        #pragma unroll
        for (int d = 0; d < 16; d++) {
            acc.x = fmaf(f[d], w[d].x, acc.x);
            acc.y = fmaf(f[d], w[d].y, acc.y);
            acc.z = fmaf(f[d], w[d].z, acc.z);
            acc.w = fmaf(f[d], w[d].w, acc.w);
        }
        if (!isV) { acc.x *= pscale; acc.y *= pscale; acc.z *= pscale; acc.w *= pscale; }
        *(uint2*)(d_kvrel + ((size_t)n*RR + r)*256 + (isV ? 128 : 0) + h*16 + f0) = f4_to_h4(acc);
    }
}

// ---------------- edge phase: warp-per-dst, online softmax ---------------------
__device__ __forceinline__ void edge_step(uint2 kr, uint2 vr, const float4 q4,
                                          float& m, float& s, float4& acc) {
    const unsigned full = 0xffffffffu;
    float4 k4 = h4_to_f4(kr);
    float4 v4 = h4_to_f4(vr);
    float p = q4.x*k4.x + q4.y*k4.y + q4.z*k4.z + q4.w*k4.w;
    p += __shfl_xor_sync(full, p, 1);
    p += __shfl_xor_sync(full, p, 2);
    float mn = fmaxf(m, p);
    float corr = __expf(m - mn);
    float w = __expf(p - mn);
    s = s*corr + w;
    acc.x = fmaf(w, v4.x, acc.x*corr);
    acc.y = fmaf(w, v4.y, acc.y*corr);
    acc.z = fmaf(w, v4.z, acc.z*corr);
    acc.w = fmaf(w, v4.w, acc.w*corr);
    m = mn;
}

__global__ void k_edge() {
    const int n = (blockIdx.x*blockDim.x + threadIdx.x) >> 5;
    if (n >= NN) return;
    const int lane = threadIdx.x & 31;

    const int ip = d_iperm[n];
    float4 q4 = h4_to_f4(*(const uint2*)(d_qh + (size_t)ip*128 + lane*4));
    const int beg = d_off[n], end = d_off[n+1];

    float m = -1e30f, s = 0.f;
    float4 acc = make_float4(0.f,0.f,0.f,0.f);

    int e = beg;
    for (; e + 1 < end; e += 2) {
        int pk0 = d_epack[e], pk1 = d_epack[e+1];
        const __half* b0 = d_kvrel + (size_t)pk0*256;
        const __half* b1 = d_kvrel + (size_t)pk1*256;
        uint2 k0 = *(const uint2*)(b0 + lane*4);
        uint2 v0 = *(const uint2*)(b0 + 128 + lane*4);
        uint2 k1 = *(const uint2*)(b1 + lane*4);
        uint2 v1 = *(const uint2*)(b1 + 128 + lane*4);
        edge_step(k0, v0, q4, m, s, acc);
        edge_step(k1, v1, q4, m, s, acc);
    }
    if (e < end) {
        int pk0 = d_epack[e];
        const __half* b0 = d_kvrel + (size_t)pk0*256;
        uint2 k0 = *(const uint2*)(b0 + lane*4);
        uint2 v0 = *(const uint2*)(b0 + 128 + lane*4);
        edge_step(k0, v0, q4, m, s, acc);
    }
    float inv = 1.0f / fmaxf(s, 1e-9f);
    acc.x *= inv; acc.y *= inv; acc.z *= inv; acc.w *= inv;
    ((float4*)d_agg)[(size_t)ip*32 + lane] = acc;
}

// ---------------- combine ------------------------------------------------------
__global__ void k_combine1(const float* __restrict__ skip,
                           const float* __restrict__ gamma,
                           const float* __restrict__ beta) {
    const int p = (blockIdx.x*blockDim.x + threadIdx.x) >> 5;
    if (p >= NP) return;
    const int lane = threadIdx.x & 31;
    const unsigned full = 0xffffffffu;
    int t = (p >= d_topad[1]) + (p >= d_topad[2]);
    float alpha = 1.0f / (1.0f + __expf(-skip[t]));
    float4 tr = ((const float4*)d_trans)[(size_t)p*32 + lane];
    float4 hx = ((const float4*)d_h0)[(size_t)p*32 + lane];
    float ia = 1.0f - alpha;
    float4 o;
    o.x = tr.x*alpha + hx.x*ia;
    o.y = tr.y*alpha + hx.y*ia;
    o.z = tr.z*alpha + hx.z*ia;
    o.w = tr.w*alpha + hx.w*ia;
    float sm = o.x + o.y + o.z + o.w;
    float sq = o.x*o.x + o.y*o.y + o.z*o.z + o.w*o.w;
    #pragma unroll
    for (int d = 16; d; d >>= 1) {
        sm += __shfl_xor_sync(full, sm, d);
        sq += __shfl_xor_sync(full, sq, d);
    }
    float mean = sm * (1.0f/128.0f);
    float var  = sq * (1.0f/128.0f) - mean*mean;
    float rstd = rsqrtf(var + 1e-5f);
    float4 g4 = ((const float4*)gamma)[t*32 + lane];
    float4 b4 = ((const float4*)beta)[t*32 + lane];
    float4 y;
    y.x = fmaxf((o.x-mean)*rstd*g4.x + b4.x, 0.f);
    y.y = fmaxf((o.y-mean)*rstd*g4.y + b4.y, 0.f);
    y.z = fmaxf((o.z-mean)*rstd*g4.z + b4.z, 0.f);
    y.w = fmaxf((o.w-mean)*rstd*g4.w + b4.w, 0.f);
    ((float4*)d_h1)[(size_t)p*32 + lane] = y;
}

__global__ void k_combine2(const float* __restrict__ skip, float* __restrict__ out) {
    const int p = (blockIdx.x*blockDim.x + threadIdx.x) >> 5;
    if (p >= NP) return;
    const int lane = threadIdx.x & 31;
    int node = d_nperm[p];
    if (node < 0) return;
    int t = (p >= d_topad[1]) + (p >= d_topad[2]);
    float alpha = 1.0f / (1.0f + __expf(-skip[t]));
    float ia = 1.0f - alpha;
    float4 tr = ((const float4*)d_trans)[(size_t)p*32 + lane];
    float4 hx = ((const float4*)d_h1)[(size_t)p*32 + lane];
    float4 o;
    o.x = tr.x*alpha + hx.x*ia;
    o.y = tr.y*alpha + hx.y*ia;
    o.z = tr.z*alpha + hx.z*ia;
    o.w = tr.w*alpha + hx.w*ia;
    ((float4*)(out + (size_t)node*128))[lane] = o;
}

// ---------------- launch --------------------------------------------------------
extern "C" void kernel_launch(void* const* d_in, const int* in_sizes, int n_in,
                              void* d_out, int out_size) {
    const float* x      = (const float*)d_in[0];
    const int*   ntypes = (const int*)d_in[1];
    const int*   ei     = (const int*)d_in[2];
    const int*   et     = (const int*)d_in[3];
    const float* Wad    = (const float*)d_in[4];
    const float* bad    = (const float*)d_in[5];
    const float* Wk     = (const float*)d_in[6];
    const float* bk     = (const float*)d_in[7];
    const float* Wq     = (const float*)d_in[8];
    const float* bq     = (const float*)d_in[9];
    const float* Wv     = (const float*)d_in[10];
    const float* bv     = (const float*)d_in[11];
    const float* Wa     = (const float*)d_in[12];
    const float* ba     = (const float*)d_in[13];
    const float* pri    = (const float*)d_in[14];
    const float* ratt   = (const float*)d_in[15];
    const float* rmsg   = (const float*)d_in[16];
    const float* skip   = (const float*)d_in[17];
    const float* gamma  = (const float*)d_in[18];
    const float* beta   = (const float*)d_in[19];
    float* out = (float*)d_out;

    const int* srcA = ei;
    const int* dstA = ei + EE;

    cudaFuncSetAttribute(k_gemm_adapt, cudaFuncAttributeMaxDynamicSharedMemorySize, GSMEM);
    cudaFuncSetAttribute(k_gemm_kqv,   cudaFuncAttributeMaxDynamicSharedMemorySize, GSMEM);
    cudaFuncSetAttribute(k_gemm_att,   cudaFuncAttributeMaxDynamicSharedMemorySize, GSMEM);

    const int SCAN_BLK = (NN + 255) / 256;
    const int WARP_BLK = (NN*32 + 255) / 256;
    const int PWARP_BLK = NP*32 / 256;

    k_init<<<(NP+255)/256, 256>>>();
    k_count<<<(EE+255)/256, 256>>>(ntypes, dstA);
    k_toffsets<<<1, 1>>>();
    k_scatter_nodes<<<(NN+255)/256, 256>>>(ntypes);
    k_scan1<<<SCAN_BLK, 256>>>();
    k_scan2<<<1, 256>>>(SCAN_BLK);
    k_scan3<<<SCAN_BLK, 256>>>();
    k_scatter_edges<<<(EE+255)/256, 256>>>(srcA, dstA, et);
    k_wprep<<<NCHUNKS, 256>>>(Wad, Wk, Wq, Wv, Wa);

    k_gemm_adapt<<<NTILE, 256, GSMEM>>>(x, bad);

    const int LB = TT*HIDD;
    const int LP = RR*HH;
    const int LR = RR*HH*DKK*DKK;

    for (int l = 0; l < 2; l++) {
        int cb = 6 + l*12;
        k_gemm_kqv<<<dim3(NTILE,3), 256, GSMEM>>>(l, cb, bk + l*LB, bq + l*LB, bv + l*LB);
        k_reltrans<<<dim3(296, 8), 256>>>(ratt + (size_t)l*LR, rmsg + (size_t)l*LR, pri + l*LP);
        k_edge<<<WARP_BLK, 256>>>();
        k_gemm_att<<<NTILE, 256, GSMEM>>>(cb + 9, ba + l*LB);
        if (l == 0) {
            k_combine1<<<PWARP_BLK, 256>>>(skip + l*TT, gamma, beta);
        } else {
            k_combine2<<<PWARP_BLK, 256>>>(skip + l*TT, out);
        }
    }
}

// round 6
// speedup vs baseline: 2.0730x; 1.0916x over previous
#include <cuda_runtime.h>
#include <cuda_fp16.h>
#include <cstdint>
#include <math.h>

#define NN   50000
#define EE   400000
#define IND  256
#define HIDD 128
#define TT   3
#define RR   4
#define HH   8
#define DKK  16
#define NP   50432          // 394 blocks * 128
#define NTILE 394
#define NCHUNKS 30          // weight pack chunks

// ---------------- scratch (static device globals) -----------------------------
__device__ float d_h0[NP*HIDD];
__device__ float d_h1[NP*HIDD];
__device__ float d_agg[NP*HIDD];
__device__ __half d_kh[NP*HIDD];
__device__ __half d_qh[NP*HIDD];
__device__ __half d_vh[NP*HIDD];
__device__ __half d_kvrel[(size_t)NP*RR*256];   // [p*4+r][0:128]=krel*pri/4, [128:256]=vrel
__device__ __half d_wpack[NCHUNKS*16384];
__device__ int   d_deg[NN];
__device__ int   d_off[NN+1];
__device__ int   d_cursor[NN];
__device__ int   d_epack[EE];
__device__ int   d_bsum[256];
__device__ int   d_bpre[256];
__device__ int   d_tcnt[TT];
__device__ int   d_topad[TT+1];
__device__ int   d_tcur[TT];
__device__ int   d_nperm[NP];
__device__ int   d_iperm[NN];

// ---------------- helpers -------------------------------------------------------
__device__ __forceinline__ uint32_t smem_u32(const void* p) {
    uint32_t a;
    asm("{ .reg .u64 t; cvta.to.shared.u64 t, %1; cvt.u32.u64 %0, t; }" : "=r"(a) : "l"(p));
    return a;
}
__device__ __forceinline__ void ldmatrix_x4(uint32_t* r, uint32_t addr) {
    asm volatile("ldmatrix.sync.aligned.m8n8.x4.shared.b16 {%0,%1,%2,%3}, [%4];"
                 : "=r"(r[0]), "=r"(r[1]), "=r"(r[2]), "=r"(r[3]) : "r"(addr));
}
__device__ __forceinline__ void ldmatrix_x2(uint32_t* r, uint32_t addr) {
    asm volatile("ldmatrix.sync.aligned.m8n8.x2.shared.b16 {%0,%1}, [%2];"
                 : "=r"(r[0]), "=r"(r[1]) : "r"(addr));
}
__device__ __forceinline__ void mma16816h(float* d, const uint32_t* a, const uint32_t* b) {
    asm volatile("mma.sync.aligned.m16n8k16.row.col.f32.f16.f16.f32 "
                 "{%0,%1,%2,%3}, {%4,%5,%6,%7}, {%8,%9}, {%0,%1,%2,%3};"
                 : "+f"(d[0]), "+f"(d[1]), "+f"(d[2]), "+f"(d[3])
                 : "r"(a[0]), "r"(a[1]), "r"(a[2]), "r"(a[3]), "r"(b[0]), "r"(b[1]));
}
__device__ __forceinline__ float4 h4_to_f4(uint2 u) {
    __half2 a = *reinterpret_cast<__half2*>(&u.x);
    __half2 b = *reinterpret_cast<__half2*>(&u.y);
    float2 fa = __half22float2(a), fb = __half22float2(b);
    return make_float4(fa.x, fa.y, fb.x, fb.y);
}
__device__ __forceinline__ uint2 f4_to_h4(float4 f) {
    __half2 a = __floats2half2_rn(f.x, f.y);
    __half2 b = __floats2half2_rn(f.z, f.w);
    uint2 u;
    u.x = *reinterpret_cast<uint32_t*>(&a);
    u.y = *reinterpret_cast<uint32_t*>(&b);
    return u;
}

// ---------------- setup kernels ------------------------------------------------
__global__ void k_init() {
    int i = blockIdx.x*blockDim.x + threadIdx.x;
    if (i < NP) d_nperm[i] = -1;
    if (i < NN) d_deg[i] = 0;
    if (i < TT) d_tcnt[i] = 0;
}
__global__ void k_count(const int* __restrict__ ntypes, const int* __restrict__ dst) {
    __shared__ int sh[TT];
    if (threadIdx.x < TT) sh[threadIdx.x] = 0;
    __syncthreads();
    int i = blockIdx.x*blockDim.x + threadIdx.x;
    if (i < NN) atomicAdd(&sh[ntypes[i]], 1);
    if (i < EE) atomicAdd(&d_deg[dst[i]], 1);
    __syncthreads();
    if (threadIdx.x < TT && sh[threadIdx.x]) atomicAdd(&d_tcnt[threadIdx.x], sh[threadIdx.x]);
}
__global__ void k_toffsets() {
    int run = 0;
    for (int t = 0; t < TT; t++) {
        d_topad[t] = run; d_tcur[t] = run;
        run += ((d_tcnt[t] + 127) / 128) * 128;
    }
    d_topad[TT] = run;
}
__global__ void k_scatter_nodes(const int* __restrict__ ntypes) {
    __shared__ int scnt[TT], sbase[TT];
    if (threadIdx.x < TT) scnt[threadIdx.x] = 0;
    __syncthreads();
    int i = blockIdx.x*blockDim.x + threadIdx.x;
    int t = 0, myidx = 0;
    bool valid = (i < NN);
    if (valid) { t = ntypes[i]; myidx = atomicAdd(&scnt[t], 1); }
    __syncthreads();
    if (threadIdx.x < TT) sbase[threadIdx.x] = atomicAdd(&d_tcur[threadIdx.x], scnt[threadIdx.x]);
    __syncthreads();
    if (valid) {
        int p = sbase[t] + myidx;
        d_nperm[p] = i;
        d_iperm[i] = p;
    }
}
__device__ __forceinline__ int block_scan_incl(int x, int* wsum) {
    unsigned full = 0xffffffffu;
    int lane = threadIdx.x & 31, wid = threadIdx.x >> 5;
    int v = x;
    #pragma unroll
    for (int d = 1; d < 32; d <<= 1) {
        int t = __shfl_up_sync(full, v, d);
        if (lane >= d) v += t;
    }
    if (lane == 31) wsum[wid] = v;
    __syncthreads();
    if (threadIdx.x == 0) {
        int run = 0;
        #pragma unroll
        for (int w = 0; w < 8; w++) { int t = wsum[w]; wsum[w] = run; run += t; }
    }
    __syncthreads();
    return v + wsum[wid];
}
__global__ void k_scan1() {
    __shared__ int wsum[8];
    int i = blockIdx.x*256 + threadIdx.x;
    int x = (i < NN) ? d_deg[i] : 0;
    int inc = block_scan_incl(x, wsum);
    if (i < NN) d_off[i] = inc - x;
    if (threadIdx.x == 255) d_bsum[blockIdx.x] = inc;
}
__global__ void k_scan2(int nblocks) {
    __shared__ int wsum[8];
    int t = threadIdx.x;
    int x = (t < nblocks) ? d_bsum[t] : 0;
    int inc = block_scan_incl(x, wsum);
    d_bpre[t] = inc - x;
}
__global__ void k_scan3() {
    int i = blockIdx.x*256 + threadIdx.x;
    if (i < NN) {
        int v = d_off[i] + d_bpre[i >> 8];
        d_off[i] = v; d_cursor[i] = v;
    }
    if (i == 0) d_off[NN] = EE;
}
__global__ void k_scatter_edges(const int* __restrict__ src, const int* __restrict__ dst,
                                const int* __restrict__ et) {
    int e = blockIdx.x*blockDim.x + threadIdx.x;
    if (e < EE) {
        int pos = atomicAdd(&d_cursor[dst[e]], 1);
        d_epack[pos] = (d_iperm[src[e]] << 2) | et[e];
    }
}

// ---------------- weight pack: fp32 -> transposed fp16 --------------------------
__global__ void k_wprep(const float* __restrict__ Wad, const float* __restrict__ Wk,
                        const float* __restrict__ Wq, const float* __restrict__ Wv,
                        const float* __restrict__ Wa) {
    int c = blockIdx.x;
    const float* W; int k0 = 0;
    if (c < 6) {
        int t = c >> 1; k0 = (c & 1) * 128;
        W = Wad + (size_t)t * 256 * 128;
    } else {
        int cc = c - 6;
        int l = cc / 12, rem = cc % 12, g = rem / 3, t = rem % 3;
        const float* Wg = (g == 0) ? Wk : (g == 1) ? Wq : (g == 2) ? Wv : Wa;
        W = Wg + (size_t)l * 3 * 128 * 128 + (size_t)t * 128 * 128;
    }
    __half* oh = d_wpack + (size_t)c * 16384;
    for (int i = threadIdx.x; i < 16384; i += 256) {
        int n = i >> 7, k = i & 127;
        oh[i] = __float2half_rn(W[(size_t)(k0 + k) * 128 + n]);
    }
}

// ---------------- HMMA GEMM core (fp16, 2-term A split) -------------------------
#define SROW   136
#define OFF_AH 0
#define OFF_AL 34816
#define OFF_B  69632
#define GSMEM  104448

// GATHER: 0 contiguous, 1 gather via nperm, 2 contiguous + GELU
// EPI: 1 tanh->f32(outf), 2 f16(outh), 3 combine1(LN+ReLU->d_h1), 4 combine2(->outfinal via nperm)
template<int GATHER, int EPI>
__device__ __forceinline__ void gemm_core(const float* __restrict__ A, int nch, int cbase,
                                          const float* __restrict__ bias,
                                          float* __restrict__ outf, __half* __restrict__ outh,
                                          const float* __restrict__ hx,
                                          const float* __restrict__ skip,
                                          const float* __restrict__ gamma,
                                          const float* __restrict__ beta,
                                          float* __restrict__ outfinal) {
    extern __shared__ char smem[];
    const uint32_t sb = smem_u32(smem);
    const int tid = threadIdx.x;
    const int wid = tid >> 5, lane = tid & 31;
    const int base = blockIdx.x * 128;
    const int t = (base >= d_topad[1]) + (base >= d_topad[2]);
    const float* bt = bias + t * 128;
    const int lda = nch * 128;
    const int wm = wid & 3, wn = wid >> 2;

    float acc[2][8][4];
    #pragma unroll
    for (int mi = 0; mi < 2; mi++)
        #pragma unroll
        for (int nj = 0; nj < 8; nj++)
            #pragma unroll
            for (int e = 0; e < 4; e++) acc[mi][nj][e] = 0.f;

    const uint32_t aoff = (uint32_t)((wm*32 + (lane & 15)) * SROW + (lane >> 4) * 8) * 2;
    const int l16 = lane & 15;
    const uint32_t boff = (uint32_t)((wn*64 + (l16 & 7)) * SROW + (l16 >> 3) * 8) * 2;

    for (int kc = 0; kc < nch; kc++) {
        if (kc > 0) __syncthreads();
        {
            int chunk = cbase + t * nch + kc;
            const uint4* bsrc = (const uint4*)(d_wpack + (size_t)chunk * 16384);
            #pragma unroll
            for (int i = 0; i < 8; i++) {
                int idx = tid + i * 256;
                int n = idx >> 4, k8g = idx & 15;
                uint32_t doff = (uint32_t)(n * SROW + k8g * 8) * 2;
                *(uint4*)(smem + OFF_B + doff) = bsrc[idx];
            }
        }
        #pragma unroll
        for (int i = 0; i < 8; i++) {
            int gi = tid + i * 256;
            int row = gi >> 4;
            int k8 = (gi & 15) * 8;
            float v[8];
            if (GATHER == 1) {
                int rn = d_nperm[base + row];
                if (rn >= 0) {
                    const float4* ap = (const float4*)(A + (size_t)rn * lda + kc*128 + k8);
                    float4 a0 = ap[0], a1 = ap[1];
                    v[0]=a0.x; v[1]=a0.y; v[2]=a0.z; v[3]=a0.w;
                    v[4]=a1.x; v[5]=a1.y; v[6]=a1.z; v[7]=a1.w;
                } else {
                    #pragma unroll
                    for (int j = 0; j < 8; j++) v[j] = 0.f;
                }
            } else {
                const float4* ap = (const float4*)(A + (size_t)(base + row) * lda + kc*128 + k8);
                float4 a0 = ap[0], a1 = ap[1];
                v[0]=a0.x; v[1]=a0.y; v[2]=a0.z; v[3]=a0.w;
                v[4]=a1.x; v[5]=a1.y; v[6]=a1.z; v[7]=a1.w;
                if (GATHER == 2) {
                    #pragma unroll
                    for (int j = 0; j < 8; j++)
                        v[j] = 0.5f * v[j] * (1.0f + erff(v[j] * 0.70710678118654752f));
                }
            }
            union { __half b[8]; uint4 u; } ph, pl;
            #pragma unroll
            for (int j = 0; j < 8; j++) {
                __half h = __float2half_rn(v[j]);
                ph.b[j] = h;
                pl.b[j] = __float2half_rn(v[j] - __half2float(h));
            }
            uint32_t doff = (uint32_t)(row * SROW + k8) * 2;
            *(uint4*)(smem + OFF_AH + doff) = ph.u;
            *(uint4*)(smem + OFF_AL + doff) = pl.u;
        }
        __syncthreads();

        #pragma unroll
        for (int ks = 0; ks < 8; ks++) {
            uint32_t ah[2][4], al[2][4];
            #pragma unroll
            for (int mi = 0; mi < 2; mi++) {
                uint32_t ad = sb + aoff + (uint32_t)(mi*16*SROW + ks*16) * 2;
                ldmatrix_x4(ah[mi], ad + OFF_AH);
                ldmatrix_x4(al[mi], ad + OFF_AL);
            }
            uint32_t bf[8][2];
            #pragma unroll
            for (int nj = 0; nj < 8; nj++) {
                uint32_t bd = sb + boff + (uint32_t)(nj*8*SROW + ks*16) * 2;
                ldmatrix_x2(bf[nj], bd + OFF_B);
            }
            #pragma unroll
            for (int mi = 0; mi < 2; mi++)
                #pragma unroll
                for (int nj = 0; nj < 8; nj++) {
                    mma16816h(acc[mi][nj], ah[mi], bf[nj]);
                    mma16816h(acc[mi][nj], al[mi], bf[nj]);
                }
        }
    }
    __syncthreads();

    float* stage = (float*)smem;              // [128][132]
    #pragma unroll
    for (int mi = 0; mi < 2; mi++) {
        #pragma unroll
        for (int nj = 0; nj < 8; nj++) {
            int row = wm*32 + mi*16 + (lane >> 2);
            int col = wn*64 + nj*8 + 2*(lane & 3);
            float b0 = __ldg(&bt[col]), b1 = __ldg(&bt[col+1]);
            float v0 = acc[mi][nj][0] + b0;
            float v1 = acc[mi][nj][1] + b1;
            float v2 = acc[mi][nj][2] + b0;
            float v3 = acc[mi][nj][3] + b1;
            if (EPI == 1) { v0 = tanhf(v0); v1 = tanhf(v1); v2 = tanhf(v2); v3 = tanhf(v3); }
            stage[row*132 + col]     = v0;
            stage[row*132 + col + 1] = v1;
            stage[(row+8)*132 + col]     = v2;
            stage[(row+8)*132 + col + 1] = v3;
        }
    }
    __syncthreads();

    if (EPI == 1) {
        for (int i = tid; i < 4096; i += 256) {
            int row = i >> 5, c4 = i & 31;
            *(float4*)(outf + ((size_t)(base + row)) * 128 + c4 * 4) =
                *(const float4*)(stage + row * 132 + c4 * 4);
        }
    } else if (EPI == 2) {
        for (int i = tid; i < 4096; i += 256) {
            int row = i >> 5, c4 = i & 31;
            float4 f = *(const float4*)(stage + row * 132 + c4 * 4);
            *(uint2*)(outh + (size_t)(base + row) * 128 + c4 * 4) = f4_to_h4(f);
        }
    } else if (EPI == 3 || EPI == 4) {
        const unsigned full = 0xffffffffu;
        float alpha = 1.0f / (1.0f + __expf(-__ldg(&skip[t])));
        float ia = 1.0f - alpha;
        float4 g4, b4;
        if (EPI == 3) {
            g4 = *(const float4*)(gamma + t*128 + lane*4);
            b4 = *(const float4*)(beta  + t*128 + lane*4);
        }
        #pragma unroll
        for (int i = 0; i < 16; i++) {
            int row = wid*16 + i;
            float4 tr = *(const float4*)(stage + row*132 + lane*4);
            float4 hx4 = *(const float4*)(hx + (size_t)(base+row)*128 + lane*4);
            float4 o;
            o.x = tr.x*alpha + hx4.x*ia;
            o.y = tr.y*alpha + hx4.y*ia;
            o.z = tr.z*alpha + hx4.z*ia;
            o.w = tr.w*alpha + hx4.w*ia;
            if (EPI == 3) {
                float sm = o.x + o.y + o.z + o.w;
                float sq = o.x*o.x + o.y*o.y + o.z*o.z + o.w*o.w;
                #pragma unroll
                for (int d = 16; d; d >>= 1) {
                    sm += __shfl_xor_sync(full, sm, d);
                    sq += __shfl_xor_sync(full, sq, d);
                }
                float mean = sm * (1.0f/128.0f);
                float var  = sq * (1.0f/128.0f) - mean*mean;
                float rstd = rsqrtf(var + 1e-5f);
                float4 y;
                y.x = fmaxf((o.x-mean)*rstd*g4.x + b4.x, 0.f);
                y.y = fmaxf((o.y-mean)*rstd*g4.y + b4.y, 0.f);
                y.z = fmaxf((o.z-mean)*rstd*g4.z + b4.z, 0.f);
                y.w = fmaxf((o.w-mean)*rstd*g4.w + b4.w, 0.f);
                *(float4*)(d_h1 + (size_t)(base+row)*128 + lane*4) = y;
            } else {
                int node = d_nperm[base + row];
                if (node >= 0)
                    *(float4*)(outfinal + (size_t)node*128 + lane*4) = o;
            }
        }
    }
}

__global__ void __launch_bounds__(256,2)
k_gemm_adapt(const float* __restrict__ x, const float* __restrict__ bad) {
    gemm_core<1,1>(x, 2, 0, bad, d_h0, nullptr, nullptr, nullptr, nullptr, nullptr, nullptr);
}
__global__ void __launch_bounds__(256,2)
k_gemm_kqv(int in_code, int cb, const float* __restrict__ bk,
           const float* __restrict__ bq, const float* __restrict__ bv) {
    const float* A = in_code ? d_h1 : d_h0;
    int g = blockIdx.y;
    __half* oh = (g == 0) ? d_kh : (g == 1) ? d_qh : d_vh;
    const float* bi = (g == 0) ? bk : (g == 1) ? bq : bv;
    gemm_core<0,2>(A, 1, cb + g*3, bi, nullptr, oh, nullptr, nullptr, nullptr, nullptr, nullptr);
}
__global__ void __launch_bounds__(256,2)
k_gemm_att0(int cb9, const float* __restrict__ ba, const float* __restrict__ skip,
            const float* __restrict__ gamma, const float* __restrict__ beta) {
    gemm_core<2,3>(d_agg, 1, cb9, ba, nullptr, nullptr, d_h0, skip, gamma, beta, nullptr);
}
__global__ void __launch_bounds__(256,2)
k_gemm_att1(int cb9, const float* __restrict__ ba, const float* __restrict__ skip,
            float* __restrict__ out) {
    gemm_core<2,4>(d_agg, 1, cb9, ba, nullptr, nullptr, d_h1, skip, nullptr, nullptr, out);
}

// ---------------- per-node relation transforms (fp16 in/out) -------------------
__global__ void k_reltrans(const float* __restrict__ Ratt, const float* __restrict__ Rmsg,
                           const float* __restrict__ pri) {
    const int slot = blockIdx.y;
    const int r = slot >> 1;
    const bool isV = slot & 1;
    const __half* srcv = isV ? d_vh : d_kh;
    const float* Wh = (isV ? Rmsg : Ratt) + r*HH*DKK*DKK;

    const int lane = threadIdx.x & 31;
    const int wid  = threadIdx.x >> 5;
    const int h = lane >> 2;
    const int f0 = (lane & 3) * 4;
    const float* Wp = Wh + h*256;
    const float pscale = isV ? 1.0f : (__ldg(&pri[r*HH + h]) * 0.25f);

    float4 w[16];
    #pragma unroll
    for (int d = 0; d < 16; d++) w[d] = *(const float4*)(Wp + d*16 + f0);

    const int wpb = blockDim.x >> 5;
    for (int n = blockIdx.x*wpb + wid; n < NP; n += gridDim.x*wpb) {
        uint4 raw0 = *(const uint4*)(srcv + (size_t)n*128 + h*16);
        uint4 raw1 = *(const uint4*)(srcv + (size_t)n*128 + h*16 + 8);
        float f[16];
        {
            const __half2* hp0 = reinterpret_cast<const __half2*>(&raw0);
            const __half2* hp1 = reinterpret_cast<const __half2*>(&raw1);
            #pragma unroll
            for (int j = 0; j < 4; j++) {
                float2 t2 = __half22float2(hp0[j]);
                f[2*j] = t2.x; f[2*j+1] = t2.y;
                float2 u2 = __half22float2(hp1[j]);
                f[8+2*j] = u2.x; f[8+2*j+1] = u2.y;
            }
        }
        float4 acc = make_float4(0.f,0.f,0.f,0.f);
        #pragma unroll
        for (int d = 0; d < 16; d++) {
            acc.x = fmaf(f[d], w[d].x, acc.x);
            acc.y = fmaf(f[d], w[d].y, acc.y);
            acc.z = fmaf(f[d], w[d].z, acc.z);
            acc.w = fmaf(f[d], w[d].w, acc.w);
        }
        if (!isV) { acc.x *= pscale; acc.y *= pscale; acc.z *= pscale; acc.w *= pscale; }
        *(uint2*)(d_kvrel + ((size_t)n*RR + r)*256 + (isV ? 128 : 0) + h*16 + f0) = f4_to_h4(acc);
    }
}

// ---------------- edge phase: warp-per-dst, online softmax ---------------------
__device__ __forceinline__ void edge_step(uint2 kr, uint2 vr, const float4 q4,
                                          float& m, float& s, float4& acc) {
    const unsigned full = 0xffffffffu;
    float4 k4 = h4_to_f4(kr);
    float4 v4 = h4_to_f4(vr);
    float p = q4.x*k4.x + q4.y*k4.y + q4.z*k4.z + q4.w*k4.w;
    p += __shfl_xor_sync(full, p, 1);
    p += __shfl_xor_sync(full, p, 2);
    float mn = fmaxf(m, p);
    float corr = __expf(m - mn);
    float w = __expf(p - mn);
    s = s*corr + w;
    acc.x = fmaf(w, v4.x, acc.x*corr);
    acc.y = fmaf(w, v4.y, acc.y*corr);
    acc.z = fmaf(w, v4.z, acc.z*corr);
    acc.w = fmaf(w, v4.w, acc.w*corr);
    m = mn;
}

__global__ void k_edge() {
    const int n = (blockIdx.x*blockDim.x + threadIdx.x) >> 5;
    if (n >= NN) return;
    const int lane = threadIdx.x & 31;

    const int ip = d_iperm[n];
    float4 q4 = h4_to_f4(*(const uint2*)(d_qh + (size_t)ip*128 + lane*4));
    const int beg = d_off[n], end = d_off[n+1];

    float m = -1e30f, s = 0.f;
    float4 acc = make_float4(0.f,0.f,0.f,0.f);

    int e = beg;
    for (; e + 1 < end; e += 2) {
        int pk0 = d_epack[e], pk1 = d_epack[e+1];
        const __half* b0 = d_kvrel + (size_t)pk0*256;
        const __half* b1 = d_kvrel + (size_t)pk1*256;
        uint2 k0 = *(const uint2*)(b0 + lane*4);
        uint2 v0 = *(const uint2*)(b0 + 128 + lane*4);
        uint2 k1 = *(const uint2*)(b1 + lane*4);
        uint2 v1 = *(const uint2*)(b1 + 128 + lane*4);
        edge_step(k0, v0, q4, m, s, acc);
        edge_step(k1, v1, q4, m, s, acc);
    }
    if (e < end) {
        int pk0 = d_epack[e];
        const __half* b0 = d_kvrel + (size_t)pk0*256;
        uint2 k0 = *(const uint2*)(b0 + lane*4);
        uint2 v0 = *(const uint2*)(b0 + 128 + lane*4);
        edge_step(k0, v0, q4, m, s, acc);
    }
    float inv = 1.0f / fmaxf(s, 1e-9f);
    acc.x *= inv; acc.y *= inv; acc.z *= inv; acc.w *= inv;
    ((float4*)d_agg)[(size_t)ip*32 + lane] = acc;
}

// ---------------- launch --------------------------------------------------------
extern "C" void kernel_launch(void* const* d_in, const int* in_sizes, int n_in,
                              void* d_out, int out_size) {
    const float* x      = (const float*)d_in[0];
    const int*   ntypes = (const int*)d_in[1];
    const int*   ei     = (const int*)d_in[2];
    const int*   et     = (const int*)d_in[3];
    const float* Wad    = (const float*)d_in[4];
    const float* bad    = (const float*)d_in[5];
    const float* Wk     = (const float*)d_in[6];
    const float* bk     = (const float*)d_in[7];
    const float* Wq     = (const float*)d_in[8];
    const float* bq     = (const float*)d_in[9];
    const float* Wv     = (const float*)d_in[10];
    const float* bv     = (const float*)d_in[11];
    const float* Wa     = (const float*)d_in[12];
    const float* ba     = (const float*)d_in[13];
    const float* pri    = (const float*)d_in[14];
    const float* ratt   = (const float*)d_in[15];
    const float* rmsg   = (const float*)d_in[16];
    const float* skip   = (const float*)d_in[17];
    const float* gamma  = (const float*)d_in[18];
    const float* beta   = (const float*)d_in[19];
    float* out = (float*)d_out;

    const int* srcA = ei;
    const int* dstA = ei + EE;

    cudaFuncSetAttribute(k_gemm_adapt, cudaFuncAttributeMaxDynamicSharedMemorySize, GSMEM);
    cudaFuncSetAttribute(k_gemm_kqv,   cudaFuncAttributeMaxDynamicSharedMemorySize, GSMEM);
    cudaFuncSetAttribute(k_gemm_att0,  cudaFuncAttributeMaxDynamicSharedMemorySize, GSMEM);
    cudaFuncSetAttribute(k_gemm_att1,  cudaFuncAttributeMaxDynamicSharedMemorySize, GSMEM);

    const int SCAN_BLK = (NN + 255) / 256;
    const int WARP_BLK = (NN*32 + 255) / 256;

    k_init<<<(NP+255)/256, 256>>>();
    k_count<<<(EE+255)/256, 256>>>(ntypes, dstA);
    k_toffsets<<<1, 1>>>();
    k_scatter_nodes<<<(NN+255)/256, 256>>>(ntypes);
    k_scan1<<<SCAN_BLK, 256>>>();
    k_scan2<<<1, 256>>>(SCAN_BLK);
    k_scan3<<<SCAN_BLK, 256>>>();
    k_scatter_edges<<<(EE+255)/256, 256>>>(srcA, dstA, et);
    k_wprep<<<NCHUNKS, 256>>>(Wad, Wk, Wq, Wv, Wa);

    k_gemm_adapt<<<NTILE, 256, GSMEM>>>(x, bad);

    const int LB = TT*HIDD;
    const int LP = RR*HH;
    const int LR = RR*HH*DKK*DKK;

    for (int l = 0; l < 2; l++) {
        int cb = 6 + l*12;
        k_gemm_kqv<<<dim3(NTILE,3), 256, GSMEM>>>(l, cb, bk + l*LB, bq + l*LB, bv + l*LB);
        k_reltrans<<<dim3(296, 8), 256>>>(ratt + (size_t)l*LR, rmsg + (size_t)l*LR, pri + l*LP);
        k_edge<<<WARP_BLK, 256>>>();
        if (l == 0) {
            k_gemm_att0<<<NTILE, 256, GSMEM>>>(cb + 9, ba + l*LB, skip + l*TT, gamma, beta);
        } else {
            k_gemm_att1<<<NTILE, 256, GSMEM>>>(cb + 9, ba + l*LB, skip + l*TT, out);
        }
    }
}